// round 13
// baseline (speedup 1.0000x reference)
#include <cuda_runtime.h>
#include <cuda_fp16.h>
#include <cstdint>

// Problem constants
constexpr int Bb   = 6;
constexpr int T    = 1024;
constexpr int DIN  = 256;
constexpr int DOUT = 512;
constexpr int G    = 8;
constexpr int KSP  = DIN * G;   // 2048

// ---------------------------------------------------------------------------
// Device scratch
// ---------------------------------------------------------------------------
__device__ __align__(16) float   g_xn2[T * DIN];             // LN'd batch 2 (dog)
__device__ __align__(16) __half  g_silu[T * DIN];            // fp16 silu (batch 3)
__device__ __align__(16) __half  g_basis[4ull * T * KSP];    // fp16 basis, slots 0..3
__device__ __align__(16) __half  g_sw[DOUT * KSP];           // fp16 spline weight
__device__ __align__(16) __half  g_bw[DOUT * DIN];           // fp16 base weight

// ---------------------------------------------------------------------------
// Helpers
// ---------------------------------------------------------------------------
__device__ __forceinline__ uint32_t hpack2(__half a, __half b)
{
    __half2 p = __halves2half2(a, b);
    return *reinterpret_cast<uint32_t*>(&p);
}

__device__ __forceinline__ uint32_t smem_u32(const void* p)
{
    uint32_t a;
    asm("{ .reg .u64 t; cvta.to.shared.u64 t, %1; cvt.u32.u64 %0, t; }" : "=r"(a) : "l"(p));
    return a;
}

__device__ __forceinline__ void cpa(uint32_t d, const void* s)
{
    asm volatile("cp.async.cg.shared.global [%0], [%1], 16;" :: "r"(d), "l"(s));
}
#define CP_COMMIT() asm volatile("cp.async.commit_group;" ::: "memory")
#define CP_WAIT1()  asm volatile("cp.async.wait_group 1;"  ::: "memory")
#define CP_WAIT0()  asm volatile("cp.async.wait_group 0;"  ::: "memory")

#define LDSM_X4(R0,R1,R2,R3,ADDR) \
    asm volatile("ldmatrix.sync.aligned.m8n8.x4.shared.b16 {%0,%1,%2,%3}, [%4];" \
        : "=r"(R0), "=r"(R1), "=r"(R2), "=r"(R3) : "r"(ADDR))

__device__ __forceinline__ void mma16816(float* c, const uint32_t* a, const uint32_t* b)
{
    asm volatile(
        "mma.sync.aligned.m16n8k16.row.col.f32.f16.f16.f32 "
        "{%0,%1,%2,%3}, {%4,%5,%6,%7}, {%8,%9}, {%0,%1,%2,%3};"
        : "+f"(c[0]), "+f"(c[1]), "+f"(c[2]), "+f"(c[3])
        : "r"(a[0]), "r"(a[1]), "r"(a[2]), "r"(a[3]), "r"(b[0]), "r"(b[1]));
}

// Packed f32x2 (Blackwell)
__device__ __forceinline__ float2 f2fma(float2 a, float2 b, float2 c)
{
    float2 d;
    asm("fma.rn.f32x2 %0, %1, %2, %3;"
        : "=l"(reinterpret_cast<unsigned long long&>(d))
        : "l"(reinterpret_cast<unsigned long long&>(a)),
          "l"(reinterpret_cast<unsigned long long&>(b)),
          "l"(reinterpret_cast<unsigned long long&>(c)));
    return d;
}
__device__ __forceinline__ float2 f2mul(float2 a, float2 b)
{
    float2 d;
    asm("mul.rn.f32x2 %0, %1, %2;"
        : "=l"(reinterpret_cast<unsigned long long&>(d))
        : "l"(reinterpret_cast<unsigned long long&>(a)),
          "l"(reinterpret_cast<unsigned long long&>(b)));
    return d;
}

// ---------------------------------------------------------------------------
// Kernel 1: fused prep (unchanged from R10).
// ---------------------------------------------------------------------------
constexpr int LN_ROW_BLOCKS = Bb * T / 8;                 // 768
constexpr int NSP       = DOUT * KSP;                     // 1048576
constexpr int WS_ELEMS  = NSP + DOUT * DIN;               // 1179648
constexpr int WS_BLOCKS = WS_ELEMS / 1024;                // 1152
constexpr int PREP_BLOCKS = LN_ROW_BLOCKS + WS_BLOCKS;    // 1920

__global__ void prep_kernel(const float* __restrict__ X,
                            const float* __restrict__ w,
                            const float* __restrict__ bias,
                            const float* __restrict__ spline_w,
                            const float* __restrict__ base_w,
                            const float* __restrict__ grid_rbf,
                            const float* __restrict__ grid_bs)
{
    int bid = blockIdx.x;
    int tid = threadIdx.x;

    if (bid >= LN_ROW_BLOCKS) {
        int slot4 = (bid - LN_ROW_BLOCKS) * 256 + tid;
        int idx = slot4 * 4;
        const float* src = (idx < NSP) ? (spline_w + idx) : (base_w + (idx - NSP));
        float4 v = *reinterpret_cast<const float4*>(src);
        uint2 uh = make_uint2(hpack2(__float2half_rn(v.x), __float2half_rn(v.y)),
                              hpack2(__float2half_rn(v.z), __float2half_rn(v.w)));
        if (idx < NSP) {
            *reinterpret_cast<uint2*>(g_sw + idx) = uh;
        } else {
            *reinterpret_cast<uint2*>(g_bw + (idx - NSP)) = uh;
        }
        return;
    }

    int wid  = tid >> 5, lane = tid & 31;
    int row  = bid * 8 + wid;
    int bb   = row >> 10;
    int t    = row & 1023;
    const float* Xr = X + (size_t)row * DIN;

    float v[8];
    float s = 0.f, s2 = 0.f;
    #pragma unroll
    for (int j = 0; j < 8; j++) {
        v[j] = Xr[j * 32 + lane];
        s  += v[j];
        s2 += v[j] * v[j];
    }
    #pragma unroll
    for (int off = 16; off; off >>= 1) {
        s  += __shfl_xor_sync(0xffffffffu, s,  off);
        s2 += __shfl_xor_sync(0xffffffffu, s2, off);
    }
    float mu = s * (1.f / DIN);
    float rv = rsqrtf(s2 * (1.f / DIN) - mu * mu + 1e-5f);

    if (bb == 2) {
        #pragma unroll
        for (int j = 0; j < 8; j++) {
            int i = j * 32 + lane;
            float xn = (v[j] - mu) * rv * w[i] + bias[i];
            g_xn2[(size_t)t * DIN + i] = xn;
        }
        return;
    }
    if (bb == 3) {
        #pragma unroll
        for (int j = 0; j < 8; j++) {
            int i = j * 32 + lane;
            float xn = (v[j] - mu) * rv * w[i] + bias[i];
            float sig = 1.f / (1.f + __expf(-xn));
            g_silu[(size_t)t * DIN + i] = __float2half_rn(xn * sig);
        }
        return;
    }

    int slot = (bb == 0) ? 0 : (bb == 1) ? 1 : (bb == 4) ? 2 : 3;
    bool rbf = (bb == 0 || bb == 4);

    float gb[12], r1 = 0.f, r2 = 0.f, r3 = 0.f, gr[G];
    if (rbf) {
        #pragma unroll
        for (int g = 0; g < G; g++) gr[g] = __ldg(&grid_rbf[g]);
    } else {
        #pragma unroll
        for (int j = 0; j < 12; j++) gb[j] = __ldg(&grid_bs[j]);
        r1 = __fdividef(1.f, gb[1] - gb[0]);
        r2 = __fdividef(1.f, gb[2] - gb[0]);
        r3 = __fdividef(1.f, gb[3] - gb[0]);
    }

    #pragma unroll
    for (int j = 0; j < 8; j++) {
        int i = j * 32 + lane;
        float xn = (v[j] - mu) * rv * w[i] + bias[i];
        __half h[G];
        if (rbf) {
            const float invd = 7.f / 3.f;
            const float c    = -1.4426950408889634f;
            #pragma unroll
            for (int g = 0; g < G; g++) {
                float d = (xn - gr[g]) * invd;
                h[g] = __float2half_rn(exp2f(d * d * c));
            }
        } else {
            float bsv[11];
            #pragma unroll
            for (int k = 0; k < 11; k++)
                bsv[k] = (xn >= gb[k] && xn < gb[k + 1]) ? 1.f : 0.f;
            #pragma unroll
            for (int k = 0; k <= 9; k++)
                bsv[k] = (xn - gb[k]) * r1 * bsv[k] + (gb[k + 2] - xn) * r1 * bsv[k + 1];
            #pragma unroll
            for (int k = 0; k <= 8; k++)
                bsv[k] = (xn - gb[k]) * r2 * bsv[k] + (gb[k + 3] - xn) * r2 * bsv[k + 1];
            #pragma unroll
            for (int k = 0; k <= 7; k++)
                bsv[k] = (xn - gb[k]) * r3 * bsv[k] + (gb[k + 4] - xn) * r3 * bsv[k + 1];
            #pragma unroll
            for (int k = 0; k < 8; k++) h[k] = __float2half_rn(bsv[k]);
        }
        size_t off = (size_t)slot * T * KSP + (size_t)t * KSP + i * 8;
        uint4 uh = make_uint4(hpack2(h[0],h[1]), hpack2(h[2],h[3]),
                              hpack2(h[4],h[5]), hpack2(h[6],h[7]));
        *reinterpret_cast<uint4*>(g_basis + off) = uh;
    }
}

// ---------------------------------------------------------------------------
// Fat kernel: 320 gemm tiles (64x128, as R10) + 128 long dog tiles (32x128),
// interleaved 2 dog : 5 gemm over period 7 -> 448 CTAs ~= one wave at 3/SM.
// ---------------------------------------------------------------------------
constexpr int BM = 64, BN = 128, BK = 32;
constexpr int OFF_A = 0, OFF_W = 4096;
constexpr int STAGE  = 12288;
constexpr int NSTAGE = 3;
constexpr int SMEM_BYTES = 53248;            // max(gemm 36 KB, dog 52.2 KB)

constexpr int FAT_BLOCKS = 448;              // 7 * 64

__device__ __forceinline__ uint32_t swz(uint32_t row, uint32_t slot)
{
    return row * 64u + (((slot ^ ((row >> 1) & 3u)) & 3u) << 4);
}

__device__ __forceinline__ void gemm_path(int gidx, char* smem, float* __restrict__ out)
{
    uint32_t sbase = smem_u32(smem);
    int tid = threadIdx.x;

    int z, tt;
    if (gidx < 256) { z = gidx >> 6; tt = gidx & 63; }
    else            { z = 4;         tt = gidx - 256; }
    int mt = tt >> 2, nt = tt & 3;
    int bb = (z == 0) ? 0 : (z == 1) ? 1 : (z == 2) ? 4 : (z == 3) ? 5 : 3;

    const __half *A, *W;
    int K;
    if (z < 4) {
        A = g_basis + (size_t)z * T * KSP;
        W = g_sw; K = KSP;
    } else {
        A = g_silu;
        W = g_bw; K = DIN;
    }
    int m0 = mt * BM, n0 = nt * BN;
    int nc = K / BK;

    int lrow = tid >> 2, lslot = tid & 3;
    const __half* gA  = A + (size_t)(m0 + lrow) * K + lslot * 8;
    const __half* gW0 = W + (size_t)(n0 + lrow) * K + lslot * 8;
    const __half* gW1 = W + (size_t)(n0 + lrow + 64) * K + lslot * 8;
    uint32_t sA  = swz(lrow, lslot);
    uint32_t sW0 = swz(lrow, lslot);
    uint32_t sW1 = swz(lrow + 64, lslot);

    int lane = tid & 31, wid = tid >> 5;
    int wm = wid >> 2, wn = wid & 3;          // warp tile 32x32
    uint32_t lr  = lane & 15;
    uint32_t lks = lane >> 4;

    float acc[2][4][4];
    #pragma unroll
    for (int a = 0; a < 2; a++)
        #pragma unroll
        for (int b = 0; b < 4; b++)
            #pragma unroll
            for (int cc = 0; cc < 4; cc++) acc[a][b][cc] = 0.f;

    #pragma unroll
    for (int p = 0; p < 2; p++) {
        if (p < nc) {
            uint32_t sb = sbase + p * STAGE;
            int kc = p * BK;
            cpa(sb + OFF_A + sA,  gA + kc);
            cpa(sb + OFF_W + sW0, gW0 + kc);
            cpa(sb + OFF_W + sW1, gW1 + kc);
        }
        CP_COMMIT();
    }

    int st = 0;
    for (int c = 0; c < nc; c++) {
        CP_WAIT1();
        __syncthreads();

        if (c + 2 < nc) {
            int stn = (st + 2 >= NSTAGE) ? st + 2 - NSTAGE : st + 2;
            uint32_t sb = sbase + stn * STAGE;
            int kc = (c + 2) * BK;
            cpa(sb + OFF_A + sA,  gA + kc);
            cpa(sb + OFF_W + sW0, gW0 + kc);
            cpa(sb + OFF_W + sW1, gW1 + kc);
        }
        CP_COMMIT();

        uint32_t sb = sbase + st * STAGE;
        #pragma unroll
        for (int ks = 0; ks < 2; ks++) {
            uint32_t slot = 2 * ks + lks;
            uint32_t aF[2][4], bF[4][2];

            #pragma unroll
            for (int mi = 0; mi < 2; mi++) {
                uint32_t ad = sb + OFF_A + swz(wm * 32 + mi * 16 + lr, slot);
                LDSM_X4(aF[mi][0], aF[mi][1], aF[mi][2], aF[mi][3], ad);
            }
            #pragma unroll
            for (int p = 0; p < 2; p++) {
                uint32_t t0, t1, t2, t3;
                uint32_t ad = sb + OFF_W + swz(wn * 32 + p * 16 + lr, slot);
                LDSM_X4(t0, t1, t2, t3, ad);
                bF[2*p][0] = t0; bF[2*p][1] = t2;
                bF[2*p+1][0] = t1; bF[2*p+1][1] = t3;
            }
            #pragma unroll
            for (int mi = 0; mi < 2; mi++)
                #pragma unroll
                for (int ni = 0; ni < 4; ni++)
                    mma16816(acc[mi][ni], aF[mi], bF[ni]);
        }
        st = (st + 1 == NSTAGE) ? 0 : st + 1;
    }

    float* Cb = out + (size_t)bb * T * DOUT;
    int rbase = m0 + wm * 32 + (lane >> 2);
    int cbase = n0 + wn * 32 + (lane & 3) * 2;
    #pragma unroll
    for (int mi = 0; mi < 2; mi++) {
        #pragma unroll
        for (int ni = 0; ni < 4; ni++) {
            int r = rbase + mi * 16;
            int cc = cbase + ni * 8;
            *reinterpret_cast<float2*>(&Cb[(size_t)r * DOUT + cc]) =
                make_float2(acc[mi][ni][0], acc[mi][ni][1]);
            *reinterpret_cast<float2*>(&Cb[(size_t)(r + 8) * DOUT + cc]) =
                make_float2(acc[mi][ni][2], acc[mi][ni][3]);
        }
    }
}

// ---------------------------------------------------------------------------
// Dog path: 32 (o) x 128 (t) per CTA = 2 sequential 64-t blocks of the R10
// body. f32x2 packed math, LDS.128 layout.
// ---------------------------------------------------------------------------
struct DogS {
    float  xn[32][72];     // [i][t_local]
    float4 pq[32][33];     // [o_local][i]
};

__device__ __forceinline__ void dog_path(int didx, char* smem,
                                         const float* __restrict__ base_w,
                                         const float* __restrict__ scale,
                                         const float* __restrict__ trans,
                                         float* __restrict__ out)
{
    DogS* S = reinterpret_cast<DogS*>(smem);   // double buffer S[0], S[1]
    int o0 = (didx & 15) * 32;
    int t0base = (didx >> 4) * 128;            // 8 t-groups of 128
    int tid = threadIdx.x;
    int tx = tid & 31, ty = tid >> 5;
    int rX = tid >> 5, cX = tid & 31;

    const float Cc = -0.7213475204444817f;     // -0.5*log2(e)
    const float2 C2 = make_float2(Cc, Cc);

    for (int tb = 0; tb < 2; tb++) {
        int t0 = t0base + tb * 64;

        float2 acc[4];
        #pragma unroll
        for (int p = 0; p < 4; p++) acc[p] = make_float2(0.f, 0.f);

        float pxn[8], prs[4], ptr_[4], pbw[4];

        // prologue: chunk 0
        #pragma unroll
        for (int p = 0; p < 8; p++)
            pxn[p] = g_xn2[(size_t)(t0 + rX + p * 8) * DIN + cX];
        #pragma unroll
        for (int p = 0; p < 4; p++) {
            size_t oi = (size_t)(o0 + rX + p * 8) * DIN + cX;
            prs[p] = __fdividef(1.f, scale[oi]);
            ptr_[p] = trans[oi];
            pbw[p] = base_w[oi];
        }
        #pragma unroll
        for (int p = 0; p < 8; p++) S[0].xn[cX][rX + p * 8] = pxn[p];
        #pragma unroll
        for (int p = 0; p < 4; p++)
            S[0].pq[rX + p * 8][cX] = make_float4(prs[p], -ptr_[p] * prs[p], -pbw[p], 0.f);

        for (int cc = 0; cc < DIN / 32; cc++) {
            __syncthreads();
            if (cc + 1 < DIN / 32) {
                int ic = (cc + 1) * 32;
                #pragma unroll
                for (int p = 0; p < 8; p++)
                    pxn[p] = g_xn2[(size_t)(t0 + rX + p * 8) * DIN + ic + cX];
                #pragma unroll
                for (int p = 0; p < 4; p++) {
                    size_t oi = (size_t)(o0 + rX + p * 8) * DIN + ic + cX;
                    prs[p] = __fdividef(1.f, scale[oi]);
                    ptr_[p] = trans[oi];
                    pbw[p] = base_w[oi];
                }
            }

            DogS& B = S[cc & 1];
            #pragma unroll 4
            for (int i = 0; i < 32; i++) {
                float4 pq = B.pq[tx][i];
                float2 rs2  = make_float2(pq.x, pq.x);
                float2 ntr2 = make_float2(pq.y, pq.y);
                float2 nbw2 = make_float2(pq.z, pq.z);
                const float4* xp = reinterpret_cast<const float4*>(&B.xn[i][ty * 8]);
                float4 xa = xp[0];
                float4 xb = xp[1];
                float2 xs[4] = { make_float2(xa.x, xa.y), make_float2(xa.z, xa.w),
                                 make_float2(xb.x, xb.y), make_float2(xb.z, xb.w) };
                #pragma unroll
                for (int p = 0; p < 4; p++) {
                    float2 u  = f2fma(xs[p], rs2, ntr2);
                    float2 t1 = f2mul(u, C2);
                    float2 t2 = f2mul(t1, u);
                    float2 e  = make_float2(exp2f(t2.x), exp2f(t2.y));
                    float2 pe = f2mul(u, e);
                    acc[p] = f2fma(pe, nbw2, acc[p]);
                }
            }

            if (cc + 1 < DIN / 32) {
                DogS& Bn = S[(cc + 1) & 1];
                #pragma unroll
                for (int p = 0; p < 8; p++) Bn.xn[cX][rX + p * 8] = pxn[p];
                #pragma unroll
                for (int p = 0; p < 4; p++)
                    Bn.pq[rX + p * 8][cX] = make_float4(prs[p], -ptr_[p] * prs[p], -pbw[p], 0.f);
            }
        }

        #pragma unroll
        for (int p = 0; p < 4; p++) {
            int r0 = t0 + ty * 8 + 2 * p;
            out[(size_t)(2 * T + r0) * DOUT + o0 + tx]     = acc[p].x;
            out[(size_t)(2 * T + r0 + 1) * DOUT + o0 + tx] = acc[p].y;
        }
        // Safe buffer handoff between tb iterations: every warp has passed the
        // cc=7 __syncthreads, so the next prologue writes S[0] while laggards
        // only read S[1].
    }
}

__global__ void __launch_bounds__(256, 3)
fat_kernel(float* __restrict__ out,
           const float* __restrict__ base_w,
           const float* __restrict__ scale,
           const float* __restrict__ trans)
{
    extern __shared__ __align__(16) char smem[];
    int bid = blockIdx.x;
    int grp = bid / 7, rem = bid % 7;      // 448 = 7 * 64; 2 dog + 5 gemm
    if (rem == 0 || rem == 3) {
        dog_path(grp * 2 + (rem == 3 ? 1 : 0), smem, base_w, scale, trans, out);
    } else {
        int idx = (rem < 3) ? (rem - 1) : (rem - 2);   // 0..4
        gemm_path(grp * 5 + idx, smem, out);
    }
}

// ---------------------------------------------------------------------------
extern "C" void kernel_launch(void* const* d_in, const int* in_sizes, int n_in,
                              void* d_out, int out_size)
{
    const float* X        = (const float*)d_in[0];
    const float* ln_w     = (const float*)d_in[1];
    const float* ln_b     = (const float*)d_in[2];
    const float* base_w   = (const float*)d_in[3];
    const float* spline_w = (const float*)d_in[4];
    const float* scale    = (const float*)d_in[5];
    const float* trans    = (const float*)d_in[6];
    const float* grid_rbf = (const float*)d_in[7];
    const float* grid_bs  = (const float*)d_in[8];
    float* out = (float*)d_out;

    cudaFuncSetAttribute(fat_kernel, cudaFuncAttributeMaxDynamicSharedMemorySize, SMEM_BYTES);

    prep_kernel<<<PREP_BLOCKS, 256>>>(X, ln_w, ln_b, spline_w, base_w,
                                      grid_rbf, grid_bs);
    fat_kernel<<<FAT_BLOCKS, 256, SMEM_BYTES>>>(out, base_w, scale, trans);
}

// round 14
// speedup vs baseline: 1.5169x; 1.5169x over previous
#include <cuda_runtime.h>
#include <cuda_fp16.h>
#include <cstdint>

// Problem constants
constexpr int Bb   = 6;
constexpr int T    = 1024;
constexpr int DIN  = 256;
constexpr int DOUT = 512;
constexpr int G    = 8;
constexpr int KSP  = DIN * G;   // 2048

// ---------------------------------------------------------------------------
// Device scratch
// ---------------------------------------------------------------------------
__device__ __align__(16) float   g_xn2[T * DIN];             // LN'd batch 2 (dog)
__device__ __align__(16) __half  g_silu[T * DIN];            // fp16 silu (batch 3)
__device__ __align__(16) __half  g_basis[4ull * T * KSP];    // fp16 basis, slots 0..3
__device__ __align__(16) __half  g_sw[DOUT * KSP];           // fp16 spline weight
__device__ __align__(16) __half  g_bw[DOUT * DIN];           // fp16 base weight

// ---------------------------------------------------------------------------
// Helpers
// ---------------------------------------------------------------------------
__device__ __forceinline__ uint32_t hpack2(__half a, __half b)
{
    __half2 p = __halves2half2(a, b);
    return *reinterpret_cast<uint32_t*>(&p);
}

__device__ __forceinline__ uint32_t smem_u32(const void* p)
{
    uint32_t a;
    asm("{ .reg .u64 t; cvta.to.shared.u64 t, %1; cvt.u32.u64 %0, t; }" : "=r"(a) : "l"(p));
    return a;
}

__device__ __forceinline__ void cpa(uint32_t d, const void* s)
{
    asm volatile("cp.async.cg.shared.global [%0], [%1], 16;" :: "r"(d), "l"(s));
}
#define CP_COMMIT() asm volatile("cp.async.commit_group;" ::: "memory")
#define CP_WAIT1()  asm volatile("cp.async.wait_group 1;"  ::: "memory")
#define CP_WAIT0()  asm volatile("cp.async.wait_group 0;"  ::: "memory")

#define LDSM_X4(R0,R1,R2,R3,ADDR) \
    asm volatile("ldmatrix.sync.aligned.m8n8.x4.shared.b16 {%0,%1,%2,%3}, [%4];" \
        : "=r"(R0), "=r"(R1), "=r"(R2), "=r"(R3) : "r"(ADDR))

__device__ __forceinline__ void mma16816(float* c, const uint32_t* a, const uint32_t* b)
{
    asm volatile(
        "mma.sync.aligned.m16n8k16.row.col.f32.f16.f16.f32 "
        "{%0,%1,%2,%3}, {%4,%5,%6,%7}, {%8,%9}, {%0,%1,%2,%3};"
        : "+f"(c[0]), "+f"(c[1]), "+f"(c[2]), "+f"(c[3])
        : "r"(a[0]), "r"(a[1]), "r"(a[2]), "r"(a[3]), "r"(b[0]), "r"(b[1]));
}

// Packed f32x2 (Blackwell)
__device__ __forceinline__ float2 f2fma(float2 a, float2 b, float2 c)
{
    float2 d;
    asm("fma.rn.f32x2 %0, %1, %2, %3;"
        : "=l"(reinterpret_cast<unsigned long long&>(d))
        : "l"(reinterpret_cast<unsigned long long&>(a)),
          "l"(reinterpret_cast<unsigned long long&>(b)),
          "l"(reinterpret_cast<unsigned long long&>(c)));
    return d;
}
__device__ __forceinline__ float2 f2mul(float2 a, float2 b)
{
    float2 d;
    asm("mul.rn.f32x2 %0, %1, %2;"
        : "=l"(reinterpret_cast<unsigned long long&>(d))
        : "l"(reinterpret_cast<unsigned long long&>(a)),
          "l"(reinterpret_cast<unsigned long long&>(b)));
    return d;
}

// ---------------------------------------------------------------------------
// Kernel 1: fused prep (unchanged from R10).
// ---------------------------------------------------------------------------
constexpr int LN_ROW_BLOCKS = Bb * T / 8;                 // 768
constexpr int NSP       = DOUT * KSP;                     // 1048576
constexpr int WS_ELEMS  = NSP + DOUT * DIN;               // 1179648
constexpr int WS_BLOCKS = WS_ELEMS / 1024;                // 1152
constexpr int PREP_BLOCKS = LN_ROW_BLOCKS + WS_BLOCKS;    // 1920

__global__ void prep_kernel(const float* __restrict__ X,
                            const float* __restrict__ w,
                            const float* __restrict__ bias,
                            const float* __restrict__ spline_w,
                            const float* __restrict__ base_w,
                            const float* __restrict__ grid_rbf,
                            const float* __restrict__ grid_bs)
{
    int bid = blockIdx.x;
    int tid = threadIdx.x;

    if (bid >= LN_ROW_BLOCKS) {
        int slot4 = (bid - LN_ROW_BLOCKS) * 256 + tid;
        int idx = slot4 * 4;
        const float* src = (idx < NSP) ? (spline_w + idx) : (base_w + (idx - NSP));
        float4 v = *reinterpret_cast<const float4*>(src);
        uint2 uh = make_uint2(hpack2(__float2half_rn(v.x), __float2half_rn(v.y)),
                              hpack2(__float2half_rn(v.z), __float2half_rn(v.w)));
        if (idx < NSP) {
            *reinterpret_cast<uint2*>(g_sw + idx) = uh;
        } else {
            *reinterpret_cast<uint2*>(g_bw + (idx - NSP)) = uh;
        }
        return;
    }

    int wid  = tid >> 5, lane = tid & 31;
    int row  = bid * 8 + wid;
    int bb   = row >> 10;
    int t    = row & 1023;
    const float* Xr = X + (size_t)row * DIN;

    float v[8];
    float s = 0.f, s2 = 0.f;
    #pragma unroll
    for (int j = 0; j < 8; j++) {
        v[j] = Xr[j * 32 + lane];
        s  += v[j];
        s2 += v[j] * v[j];
    }
    #pragma unroll
    for (int off = 16; off; off >>= 1) {
        s  += __shfl_xor_sync(0xffffffffu, s,  off);
        s2 += __shfl_xor_sync(0xffffffffu, s2, off);
    }
    float mu = s * (1.f / DIN);
    float rv = rsqrtf(s2 * (1.f / DIN) - mu * mu + 1e-5f);

    if (bb == 2) {
        #pragma unroll
        for (int j = 0; j < 8; j++) {
            int i = j * 32 + lane;
            float xn = (v[j] - mu) * rv * w[i] + bias[i];
            g_xn2[(size_t)t * DIN + i] = xn;
        }
        return;
    }
    if (bb == 3) {
        #pragma unroll
        for (int j = 0; j < 8; j++) {
            int i = j * 32 + lane;
            float xn = (v[j] - mu) * rv * w[i] + bias[i];
            float sig = 1.f / (1.f + __expf(-xn));
            g_silu[(size_t)t * DIN + i] = __float2half_rn(xn * sig);
        }
        return;
    }

    int slot = (bb == 0) ? 0 : (bb == 1) ? 1 : (bb == 4) ? 2 : 3;
    bool rbf = (bb == 0 || bb == 4);

    float gb[12], r1 = 0.f, r2 = 0.f, r3 = 0.f, gr[G];
    if (rbf) {
        #pragma unroll
        for (int g = 0; g < G; g++) gr[g] = __ldg(&grid_rbf[g]);
    } else {
        #pragma unroll
        for (int j = 0; j < 12; j++) gb[j] = __ldg(&grid_bs[j]);
        r1 = __fdividef(1.f, gb[1] - gb[0]);
        r2 = __fdividef(1.f, gb[2] - gb[0]);
        r3 = __fdividef(1.f, gb[3] - gb[0]);
    }

    #pragma unroll
    for (int j = 0; j < 8; j++) {
        int i = j * 32 + lane;
        float xn = (v[j] - mu) * rv * w[i] + bias[i];
        __half h[G];
        if (rbf) {
            const float invd = 7.f / 3.f;
            const float c    = -1.4426950408889634f;
            #pragma unroll
            for (int g = 0; g < G; g++) {
                float d = (xn - gr[g]) * invd;
                h[g] = __float2half_rn(exp2f(d * d * c));
            }
        } else {
            float bsv[11];
            #pragma unroll
            for (int k = 0; k < 11; k++)
                bsv[k] = (xn >= gb[k] && xn < gb[k + 1]) ? 1.f : 0.f;
            #pragma unroll
            for (int k = 0; k <= 9; k++)
                bsv[k] = (xn - gb[k]) * r1 * bsv[k] + (gb[k + 2] - xn) * r1 * bsv[k + 1];
            #pragma unroll
            for (int k = 0; k <= 8; k++)
                bsv[k] = (xn - gb[k]) * r2 * bsv[k] + (gb[k + 3] - xn) * r2 * bsv[k + 1];
            #pragma unroll
            for (int k = 0; k <= 7; k++)
                bsv[k] = (xn - gb[k]) * r3 * bsv[k] + (gb[k + 4] - xn) * r3 * bsv[k + 1];
            #pragma unroll
            for (int k = 0; k < 8; k++) h[k] = __float2half_rn(bsv[k]);
        }
        size_t off = (size_t)slot * T * KSP + (size_t)t * KSP + i * 8;
        uint4 uh = make_uint4(hpack2(h[0],h[1]), hpack2(h[2],h[3]),
                              hpack2(h[4],h[5]), hpack2(h[6],h[7]));
        *reinterpret_cast<uint4*>(g_basis + off) = uh;
    }
}

// ---------------------------------------------------------------------------
// Fat kernel (R10 layout): 320 gemm tiles (64x128) + 256 dog tiles (32x64),
// interleaved 5 gemm : 4 dog over period 9 -> 576 CTAs.
// ---------------------------------------------------------------------------
constexpr int BM = 64, BN = 128, BK = 32;
constexpr int OFF_A = 0, OFF_W = 4096;
constexpr int STAGE  = 12288;
constexpr int NSTAGE = 3;
constexpr int SMEM_BYTES = 53248;            // max(gemm 36 KB, dog 52.2 KB)

constexpr int GEMM_TILES = 320;   // 256 spline + 64 base
constexpr int DOG_TILES  = 256;   // 16 o-tiles x 16 t-tiles (32 x 64)
constexpr int FAT_BLOCKS = GEMM_TILES + DOG_TILES;   // 576 = 9 * 64

__device__ __forceinline__ uint32_t swz(uint32_t row, uint32_t slot)
{
    return row * 64u + (((slot ^ ((row >> 1) & 3u)) & 3u) << 4);
}

__device__ __forceinline__ void gemm_path(int gidx, char* smem, float* __restrict__ out)
{
    uint32_t sbase = smem_u32(smem);
    int tid = threadIdx.x;

    int z, tt;
    if (gidx < 256) { z = gidx >> 6; tt = gidx & 63; }
    else            { z = 4;         tt = gidx - 256; }
    int mt = tt >> 2, nt = tt & 3;
    int bb = (z == 0) ? 0 : (z == 1) ? 1 : (z == 2) ? 4 : (z == 3) ? 5 : 3;

    const __half *A, *W;
    int K;
    if (z < 4) {
        A = g_basis + (size_t)z * T * KSP;
        W = g_sw; K = KSP;
    } else {
        A = g_silu;
        W = g_bw; K = DIN;
    }
    int m0 = mt * BM, n0 = nt * BN;
    int nc = K / BK;

    int lrow = tid >> 2, lslot = tid & 3;
    const __half* gA  = A + (size_t)(m0 + lrow) * K + lslot * 8;
    const __half* gW0 = W + (size_t)(n0 + lrow) * K + lslot * 8;
    const __half* gW1 = W + (size_t)(n0 + lrow + 64) * K + lslot * 8;
    uint32_t sA  = swz(lrow, lslot);
    uint32_t sW0 = swz(lrow, lslot);
    uint32_t sW1 = swz(lrow + 64, lslot);

    int lane = tid & 31, wid = tid >> 5;
    int wm = wid >> 2, wn = wid & 3;          // warp tile 32x32
    uint32_t lr  = lane & 15;
    uint32_t lks = lane >> 4;

    float acc[2][4][4];
    #pragma unroll
    for (int a = 0; a < 2; a++)
        #pragma unroll
        for (int b = 0; b < 4; b++)
            #pragma unroll
            for (int cc = 0; cc < 4; cc++) acc[a][b][cc] = 0.f;

    #pragma unroll
    for (int p = 0; p < 2; p++) {
        if (p < nc) {
            uint32_t sb = sbase + p * STAGE;
            int kc = p * BK;
            cpa(sb + OFF_A + sA,  gA + kc);
            cpa(sb + OFF_W + sW0, gW0 + kc);
            cpa(sb + OFF_W + sW1, gW1 + kc);
        }
        CP_COMMIT();
    }

    int st = 0;
    for (int c = 0; c < nc; c++) {
        CP_WAIT1();
        __syncthreads();

        if (c + 2 < nc) {
            int stn = (st + 2 >= NSTAGE) ? st + 2 - NSTAGE : st + 2;
            uint32_t sb = sbase + stn * STAGE;
            int kc = (c + 2) * BK;
            cpa(sb + OFF_A + sA,  gA + kc);
            cpa(sb + OFF_W + sW0, gW0 + kc);
            cpa(sb + OFF_W + sW1, gW1 + kc);
        }
        CP_COMMIT();

        uint32_t sb = sbase + st * STAGE;
        #pragma unroll
        for (int ks = 0; ks < 2; ks++) {
            uint32_t slot = 2 * ks + lks;
            uint32_t aF[2][4], bF[4][2];

            #pragma unroll
            for (int mi = 0; mi < 2; mi++) {
                uint32_t ad = sb + OFF_A + swz(wm * 32 + mi * 16 + lr, slot);
                LDSM_X4(aF[mi][0], aF[mi][1], aF[mi][2], aF[mi][3], ad);
            }
            #pragma unroll
            for (int p = 0; p < 2; p++) {
                uint32_t t0, t1, t2, t3;
                uint32_t ad = sb + OFF_W + swz(wn * 32 + p * 16 + lr, slot);
                LDSM_X4(t0, t1, t2, t3, ad);
                bF[2*p][0] = t0; bF[2*p][1] = t2;
                bF[2*p+1][0] = t1; bF[2*p+1][1] = t3;
            }
            #pragma unroll
            for (int mi = 0; mi < 2; mi++)
                #pragma unroll
                for (int ni = 0; ni < 4; ni++)
                    mma16816(acc[mi][ni], aF[mi], bF[ni]);
        }
        st = (st + 1 == NSTAGE) ? 0 : st + 1;
    }

    float* Cb = out + (size_t)bb * T * DOUT;
    int rbase = m0 + wm * 32 + (lane >> 2);
    int cbase = n0 + wn * 32 + (lane & 3) * 2;
    #pragma unroll
    for (int mi = 0; mi < 2; mi++) {
        #pragma unroll
        for (int ni = 0; ni < 4; ni++) {
            int r = rbase + mi * 16;
            int cc = cbase + ni * 8;
            *reinterpret_cast<float2*>(&Cb[(size_t)r * DOUT + cc]) =
                make_float2(acc[mi][ni][0], acc[mi][ni][1]);
            *reinterpret_cast<float2*>(&Cb[(size_t)(r + 8) * DOUT + cc]) =
                make_float2(acc[mi][ni][2], acc[mi][ni][3]);
        }
    }
}

// ---------------------------------------------------------------------------
// Dog path: 32 (o) x 64 (t) tiles, f32x2 packed math, LDS.128 layout, with a
// staged inner body: all exp args first, then back-to-back MUFU, then accum.
// ---------------------------------------------------------------------------
struct DogS {
    float  xn[32][72];     // [i][t_local]
    float4 pq[32][33];     // [o_local][i]
};

__device__ __forceinline__ void dog_path(int didx, char* smem,
                                         const float* __restrict__ base_w,
                                         const float* __restrict__ scale,
                                         const float* __restrict__ trans,
                                         float* __restrict__ out)
{
    DogS* S = reinterpret_cast<DogS*>(smem);   // double buffer S[0], S[1]
    int o0 = (didx & 15) * 32;
    int t0 = (didx >> 4) * 64;
    int tid = threadIdx.x;
    int tx = tid & 31, ty = tid >> 5;
    int rX = tid >> 5, cX = tid & 31;

    float2 acc[4];
    #pragma unroll
    for (int p = 0; p < 4; p++) acc[p] = make_float2(0.f, 0.f);
    const float Cc = -0.7213475204444817f;     // -0.5*log2(e)
    const float2 C2 = make_float2(Cc, Cc);

    float pxn[8], prs[4], ptr_[4], pbw[4];

    // prologue: chunk 0
    #pragma unroll
    for (int p = 0; p < 8; p++)
        pxn[p] = g_xn2[(size_t)(t0 + rX + p * 8) * DIN + cX];
    #pragma unroll
    for (int p = 0; p < 4; p++) {
        size_t oi = (size_t)(o0 + rX + p * 8) * DIN + cX;
        prs[p] = __fdividef(1.f, scale[oi]);
        ptr_[p] = trans[oi];
        pbw[p] = base_w[oi];
    }
    #pragma unroll
    for (int p = 0; p < 8; p++) S[0].xn[cX][rX + p * 8] = pxn[p];
    #pragma unroll
    for (int p = 0; p < 4; p++)
        S[0].pq[rX + p * 8][cX] = make_float4(prs[p], -ptr_[p] * prs[p], -pbw[p], 0.f);

    for (int cc = 0; cc < DIN / 32; cc++) {
        __syncthreads();
        if (cc + 1 < DIN / 32) {
            int ic = (cc + 1) * 32;
            #pragma unroll
            for (int p = 0; p < 8; p++)
                pxn[p] = g_xn2[(size_t)(t0 + rX + p * 8) * DIN + ic + cX];
            #pragma unroll
            for (int p = 0; p < 4; p++) {
                size_t oi = (size_t)(o0 + rX + p * 8) * DIN + ic + cX;
                prs[p] = __fdividef(1.f, scale[oi]);
                ptr_[p] = trans[oi];
                pbw[p] = base_w[oi];
            }
        }

        DogS& B = S[cc & 1];
        #pragma unroll 4
        for (int i = 0; i < 32; i++) {
            float4 pq = B.pq[tx][i];
            float2 rs2  = make_float2(pq.x, pq.x);
            float2 ntr2 = make_float2(pq.y, pq.y);
            float2 nbw2 = make_float2(pq.z, pq.z);
            const float4* xp = reinterpret_cast<const float4*>(&B.xn[i][ty * 8]);
            float4 xa = xp[0];
            float4 xb = xp[1];
            float2 xs[4] = { make_float2(xa.x, xa.y), make_float2(xa.z, xa.w),
                             make_float2(xb.x, xb.y), make_float2(xb.z, xb.w) };

            // stage 1: all exp arguments
            float2 u[4], t2[4];
            #pragma unroll
            for (int p = 0; p < 4; p++) {
                u[p]  = f2fma(xs[p], rs2, ntr2);
                t2[p] = f2mul(f2mul(u[p], C2), u[p]);
            }
            // stage 2: back-to-back MUFU
            float2 e[4];
            #pragma unroll
            for (int p = 0; p < 4; p++) {
                e[p].x = exp2f(t2[p].x);
                e[p].y = exp2f(t2[p].y);
            }
            // stage 3: accumulate
            #pragma unroll
            for (int p = 0; p < 4; p++)
                acc[p] = f2fma(f2mul(u[p], e[p]), nbw2, acc[p]);
        }

        if (cc + 1 < DIN / 32) {
            DogS& Bn = S[(cc + 1) & 1];
            #pragma unroll
            for (int p = 0; p < 8; p++) Bn.xn[cX][rX + p * 8] = pxn[p];
            #pragma unroll
            for (int p = 0; p < 4; p++)
                Bn.pq[rX + p * 8][cX] = make_float4(prs[p], -ptr_[p] * prs[p], -pbw[p], 0.f);
        }
    }

    #pragma unroll
    for (int p = 0; p < 4; p++) {
        int r0 = t0 + ty * 8 + 2 * p;
        out[(size_t)(2 * T + r0) * DOUT + o0 + tx]     = acc[p].x;
        out[(size_t)(2 * T + r0 + 1) * DOUT + o0 + tx] = acc[p].y;
    }
}

__global__ void __launch_bounds__(256, 3)
fat_kernel(float* __restrict__ out,
           const float* __restrict__ base_w,
           const float* __restrict__ scale,
           const float* __restrict__ trans)
{
    extern __shared__ __align__(16) char smem[];
    int bid = blockIdx.x;
    int grp = bid / 9, rem = bid % 9;      // 576 = 9 * 64; 5 gemm + 4 dog
    if (rem < 5) gemm_path(grp * 5 + rem, smem, out);
    else         dog_path(grp * 4 + (rem - 5), smem, base_w, scale, trans, out);
}

// ---------------------------------------------------------------------------
extern "C" void kernel_launch(void* const* d_in, const int* in_sizes, int n_in,
                              void* d_out, int out_size)
{
    const float* X        = (const float*)d_in[0];
    const float* ln_w     = (const float*)d_in[1];
    const float* ln_b     = (const float*)d_in[2];
    const float* base_w   = (const float*)d_in[3];
    const float* spline_w = (const float*)d_in[4];
    const float* scale    = (const float*)d_in[5];
    const float* trans    = (const float*)d_in[6];
    const float* grid_rbf = (const float*)d_in[7];
    const float* grid_bs  = (const float*)d_in[8];
    float* out = (float*)d_out;

    cudaFuncSetAttribute(fat_kernel, cudaFuncAttributeMaxDynamicSharedMemorySize, SMEM_BYTES);

    prep_kernel<<<PREP_BLOCKS, 256>>>(X, ln_w, ln_b, spline_w, base_w,
                                      grid_rbf, grid_bs);
    fat_kernel<<<FAT_BLOCKS, 256, SMEM_BYTES>>>(out, base_w, scale, trans);
}

// round 15
// speedup vs baseline: 1.6398x; 1.0810x over previous
#include <cuda_runtime.h>
#include <cuda_fp16.h>
#include <cstdint>

// Problem constants
constexpr int Bb   = 6;
constexpr int T    = 1024;
constexpr int DIN  = 256;
constexpr int DOUT = 512;
constexpr int G    = 8;
constexpr int KSP  = DIN * G;   // 2048

// ---------------------------------------------------------------------------
// Device scratch
// ---------------------------------------------------------------------------
__device__ __align__(16) float   g_xn2[T * DIN];             // LN'd batch 2 (dog)
__device__ __align__(16) __half  g_silu[T * DIN];            // fp16 silu (batch 3)
__device__ __align__(16) __half  g_basis[4ull * T * KSP];    // fp16 basis, slots 0..3
__device__ __align__(16) __half  g_sw[DOUT * KSP];           // fp16 spline weight
__device__ __align__(16) __half  g_bw[DOUT * DIN];           // fp16 base weight

// ---------------------------------------------------------------------------
// Helpers
// ---------------------------------------------------------------------------
__device__ __forceinline__ uint32_t hpack2(__half a, __half b)
{
    __half2 p = __halves2half2(a, b);
    return *reinterpret_cast<uint32_t*>(&p);
}

__device__ __forceinline__ uint32_t smem_u32(const void* p)
{
    uint32_t a;
    asm("{ .reg .u64 t; cvta.to.shared.u64 t, %1; cvt.u32.u64 %0, t; }" : "=r"(a) : "l"(p));
    return a;
}

__device__ __forceinline__ void cpa(uint32_t d, const void* s)
{
    asm volatile("cp.async.cg.shared.global [%0], [%1], 16;" :: "r"(d), "l"(s));
}
#define CP_COMMIT() asm volatile("cp.async.commit_group;" ::: "memory")
#define CP_WAIT1()  asm volatile("cp.async.wait_group 1;"  ::: "memory")
#define CP_WAIT0()  asm volatile("cp.async.wait_group 0;"  ::: "memory")

#define LDSM_X4(R0,R1,R2,R3,ADDR) \
    asm volatile("ldmatrix.sync.aligned.m8n8.x4.shared.b16 {%0,%1,%2,%3}, [%4];" \
        : "=r"(R0), "=r"(R1), "=r"(R2), "=r"(R3) : "r"(ADDR))

__device__ __forceinline__ void mma16816(float* c, const uint32_t* a, const uint32_t* b)
{
    asm volatile(
        "mma.sync.aligned.m16n8k16.row.col.f32.f16.f16.f32 "
        "{%0,%1,%2,%3}, {%4,%5,%6,%7}, {%8,%9}, {%0,%1,%2,%3};"
        : "+f"(c[0]), "+f"(c[1]), "+f"(c[2]), "+f"(c[3])
        : "r"(a[0]), "r"(a[1]), "r"(a[2]), "r"(a[3]), "r"(b[0]), "r"(b[1]));
}

// Packed f32x2 (Blackwell)
__device__ __forceinline__ float2 f2fma(float2 a, float2 b, float2 c)
{
    float2 d;
    asm("fma.rn.f32x2 %0, %1, %2, %3;"
        : "=l"(reinterpret_cast<unsigned long long&>(d))
        : "l"(reinterpret_cast<unsigned long long&>(a)),
          "l"(reinterpret_cast<unsigned long long&>(b)),
          "l"(reinterpret_cast<unsigned long long&>(c)));
    return d;
}
__device__ __forceinline__ float2 f2mul(float2 a, float2 b)
{
    float2 d;
    asm("mul.rn.f32x2 %0, %1, %2;"
        : "=l"(reinterpret_cast<unsigned long long&>(d))
        : "l"(reinterpret_cast<unsigned long long&>(a)),
          "l"(reinterpret_cast<unsigned long long&>(b)));
    return d;
}

// Packed fp16 exp2: one MUFU for two exponentials.
__device__ __forceinline__ float2 exp2_f16x2(float2 t)
{
    __half2 h = __float22half2_rn(t);
    uint32_t u = *reinterpret_cast<uint32_t*>(&h);
    asm("ex2.approx.f16x2 %0, %0;" : "+r"(u));
    __half2 r = *reinterpret_cast<__half2*>(&u);
    return __half22float2(r);
}

// ---------------------------------------------------------------------------
// Kernel 1: fused prep (unchanged from R10).
// ---------------------------------------------------------------------------
constexpr int LN_ROW_BLOCKS = Bb * T / 8;                 // 768
constexpr int NSP       = DOUT * KSP;                     // 1048576
constexpr int WS_ELEMS  = NSP + DOUT * DIN;               // 1179648
constexpr int WS_BLOCKS = WS_ELEMS / 1024;                // 1152
constexpr int PREP_BLOCKS = LN_ROW_BLOCKS + WS_BLOCKS;    // 1920

__global__ void prep_kernel(const float* __restrict__ X,
                            const float* __restrict__ w,
                            const float* __restrict__ bias,
                            const float* __restrict__ spline_w,
                            const float* __restrict__ base_w,
                            const float* __restrict__ grid_rbf,
                            const float* __restrict__ grid_bs)
{
    int bid = blockIdx.x;
    int tid = threadIdx.x;

    if (bid >= LN_ROW_BLOCKS) {
        int slot4 = (bid - LN_ROW_BLOCKS) * 256 + tid;
        int idx = slot4 * 4;
        const float* src = (idx < NSP) ? (spline_w + idx) : (base_w + (idx - NSP));
        float4 v = *reinterpret_cast<const float4*>(src);
        uint2 uh = make_uint2(hpack2(__float2half_rn(v.x), __float2half_rn(v.y)),
                              hpack2(__float2half_rn(v.z), __float2half_rn(v.w)));
        if (idx < NSP) {
            *reinterpret_cast<uint2*>(g_sw + idx) = uh;
        } else {
            *reinterpret_cast<uint2*>(g_bw + (idx - NSP)) = uh;
        }
        return;
    }

    int wid  = tid >> 5, lane = tid & 31;
    int row  = bid * 8 + wid;
    int bb   = row >> 10;
    int t    = row & 1023;
    const float* Xr = X + (size_t)row * DIN;

    float v[8];
    float s = 0.f, s2 = 0.f;
    #pragma unroll
    for (int j = 0; j < 8; j++) {
        v[j] = Xr[j * 32 + lane];
        s  += v[j];
        s2 += v[j] * v[j];
    }
    #pragma unroll
    for (int off = 16; off; off >>= 1) {
        s  += __shfl_xor_sync(0xffffffffu, s,  off);
        s2 += __shfl_xor_sync(0xffffffffu, s2, off);
    }
    float mu = s * (1.f / DIN);
    float rv = rsqrtf(s2 * (1.f / DIN) - mu * mu + 1e-5f);

    if (bb == 2) {
        #pragma unroll
        for (int j = 0; j < 8; j++) {
            int i = j * 32 + lane;
            float xn = (v[j] - mu) * rv * w[i] + bias[i];
            g_xn2[(size_t)t * DIN + i] = xn;
        }
        return;
    }
    if (bb == 3) {
        #pragma unroll
        for (int j = 0; j < 8; j++) {
            int i = j * 32 + lane;
            float xn = (v[j] - mu) * rv * w[i] + bias[i];
            float sig = 1.f / (1.f + __expf(-xn));
            g_silu[(size_t)t * DIN + i] = __float2half_rn(xn * sig);
        }
        return;
    }

    int slot = (bb == 0) ? 0 : (bb == 1) ? 1 : (bb == 4) ? 2 : 3;
    bool rbf = (bb == 0 || bb == 4);

    float gb[12], r1 = 0.f, r2 = 0.f, r3 = 0.f, gr[G];
    if (rbf) {
        #pragma unroll
        for (int g = 0; g < G; g++) gr[g] = __ldg(&grid_rbf[g]);
    } else {
        #pragma unroll
        for (int j = 0; j < 12; j++) gb[j] = __ldg(&grid_bs[j]);
        r1 = __fdividef(1.f, gb[1] - gb[0]);
        r2 = __fdividef(1.f, gb[2] - gb[0]);
        r3 = __fdividef(1.f, gb[3] - gb[0]);
    }

    #pragma unroll
    for (int j = 0; j < 8; j++) {
        int i = j * 32 + lane;
        float xn = (v[j] - mu) * rv * w[i] + bias[i];
        __half h[G];
        if (rbf) {
            const float invd = 7.f / 3.f;
            const float c    = -1.4426950408889634f;
            #pragma unroll
            for (int g = 0; g < G; g++) {
                float d = (xn - gr[g]) * invd;
                h[g] = __float2half_rn(exp2f(d * d * c));
            }
        } else {
            float bsv[11];
            #pragma unroll
            for (int k = 0; k < 11; k++)
                bsv[k] = (xn >= gb[k] && xn < gb[k + 1]) ? 1.f : 0.f;
            #pragma unroll
            for (int k = 0; k <= 9; k++)
                bsv[k] = (xn - gb[k]) * r1 * bsv[k] + (gb[k + 2] - xn) * r1 * bsv[k + 1];
            #pragma unroll
            for (int k = 0; k <= 8; k++)
                bsv[k] = (xn - gb[k]) * r2 * bsv[k] + (gb[k + 3] - xn) * r2 * bsv[k + 1];
            #pragma unroll
            for (int k = 0; k <= 7; k++)
                bsv[k] = (xn - gb[k]) * r3 * bsv[k] + (gb[k + 4] - xn) * r3 * bsv[k + 1];
            #pragma unroll
            for (int k = 0; k < 8; k++) h[k] = __float2half_rn(bsv[k]);
        }
        size_t off = (size_t)slot * T * KSP + (size_t)t * KSP + i * 8;
        uint4 uh = make_uint4(hpack2(h[0],h[1]), hpack2(h[2],h[3]),
                              hpack2(h[4],h[5]), hpack2(h[6],h[7]));
        *reinterpret_cast<uint4*>(g_basis + off) = uh;
    }
}

// ---------------------------------------------------------------------------
// Fat kernel (R10 layout): 320 gemm tiles (64x128) + 256 dog tiles (32x64),
// interleaved 5 gemm : 4 dog over period 9 -> 576 CTAs.
// ---------------------------------------------------------------------------
constexpr int BM = 64, BN = 128, BK = 32;
constexpr int OFF_A = 0, OFF_W = 4096;
constexpr int STAGE  = 12288;
constexpr int NSTAGE = 3;
constexpr int SMEM_BYTES = 53248;            // max(gemm 36 KB, dog 52.2 KB)

constexpr int GEMM_TILES = 320;   // 256 spline + 64 base
constexpr int DOG_TILES  = 256;   // 16 o-tiles x 16 t-tiles (32 x 64)
constexpr int FAT_BLOCKS = GEMM_TILES + DOG_TILES;   // 576 = 9 * 64

__device__ __forceinline__ uint32_t swz(uint32_t row, uint32_t slot)
{
    return row * 64u + (((slot ^ ((row >> 1) & 3u)) & 3u) << 4);
}

__device__ __forceinline__ void gemm_path(int gidx, char* smem, float* __restrict__ out)
{
    uint32_t sbase = smem_u32(smem);
    int tid = threadIdx.x;

    int z, tt;
    if (gidx < 256) { z = gidx >> 6; tt = gidx & 63; }
    else            { z = 4;         tt = gidx - 256; }
    int mt = tt >> 2, nt = tt & 3;
    int bb = (z == 0) ? 0 : (z == 1) ? 1 : (z == 2) ? 4 : (z == 3) ? 5 : 3;

    const __half *A, *W;
    int K;
    if (z < 4) {
        A = g_basis + (size_t)z * T * KSP;
        W = g_sw; K = KSP;
    } else {
        A = g_silu;
        W = g_bw; K = DIN;
    }
    int m0 = mt * BM, n0 = nt * BN;
    int nc = K / BK;

    int lrow = tid >> 2, lslot = tid & 3;
    const __half* gA  = A + (size_t)(m0 + lrow) * K + lslot * 8;
    const __half* gW0 = W + (size_t)(n0 + lrow) * K + lslot * 8;
    const __half* gW1 = W + (size_t)(n0 + lrow + 64) * K + lslot * 8;
    uint32_t sA  = swz(lrow, lslot);
    uint32_t sW0 = swz(lrow, lslot);
    uint32_t sW1 = swz(lrow + 64, lslot);

    int lane = tid & 31, wid = tid >> 5;
    int wm = wid >> 2, wn = wid & 3;          // warp tile 32x32
    uint32_t lr  = lane & 15;
    uint32_t lks = lane >> 4;

    float acc[2][4][4];
    #pragma unroll
    for (int a = 0; a < 2; a++)
        #pragma unroll
        for (int b = 0; b < 4; b++)
            #pragma unroll
            for (int cc = 0; cc < 4; cc++) acc[a][b][cc] = 0.f;

    #pragma unroll
    for (int p = 0; p < 2; p++) {
        if (p < nc) {
            uint32_t sb = sbase + p * STAGE;
            int kc = p * BK;
            cpa(sb + OFF_A + sA,  gA + kc);
            cpa(sb + OFF_W + sW0, gW0 + kc);
            cpa(sb + OFF_W + sW1, gW1 + kc);
        }
        CP_COMMIT();
    }

    int st = 0;
    for (int c = 0; c < nc; c++) {
        CP_WAIT1();
        __syncthreads();

        if (c + 2 < nc) {
            int stn = (st + 2 >= NSTAGE) ? st + 2 - NSTAGE : st + 2;
            uint32_t sb = sbase + stn * STAGE;
            int kc = (c + 2) * BK;
            cpa(sb + OFF_A + sA,  gA + kc);
            cpa(sb + OFF_W + sW0, gW0 + kc);
            cpa(sb + OFF_W + sW1, gW1 + kc);
        }
        CP_COMMIT();

        uint32_t sb = sbase + st * STAGE;
        #pragma unroll
        for (int ks = 0; ks < 2; ks++) {
            uint32_t slot = 2 * ks + lks;
            uint32_t aF[2][4], bF[4][2];

            #pragma unroll
            for (int mi = 0; mi < 2; mi++) {
                uint32_t ad = sb + OFF_A + swz(wm * 32 + mi * 16 + lr, slot);
                LDSM_X4(aF[mi][0], aF[mi][1], aF[mi][2], aF[mi][3], ad);
            }
            #pragma unroll
            for (int p = 0; p < 2; p++) {
                uint32_t t0, t1, t2, t3;
                uint32_t ad = sb + OFF_W + swz(wn * 32 + p * 16 + lr, slot);
                LDSM_X4(t0, t1, t2, t3, ad);
                bF[2*p][0] = t0; bF[2*p][1] = t2;
                bF[2*p+1][0] = t1; bF[2*p+1][1] = t3;
            }
            #pragma unroll
            for (int mi = 0; mi < 2; mi++)
                #pragma unroll
                for (int ni = 0; ni < 4; ni++)
                    mma16816(acc[mi][ni], aF[mi], bF[ni]);
        }
        st = (st + 1 == NSTAGE) ? 0 : st + 1;
    }

    float* Cb = out + (size_t)bb * T * DOUT;
    int rbase = m0 + wm * 32 + (lane >> 2);
    int cbase = n0 + wn * 32 + (lane & 3) * 2;
    #pragma unroll
    for (int mi = 0; mi < 2; mi++) {
        #pragma unroll
        for (int ni = 0; ni < 4; ni++) {
            int r = rbase + mi * 16;
            int cc = cbase + ni * 8;
            *reinterpret_cast<float2*>(&Cb[(size_t)r * DOUT + cc]) =
                make_float2(acc[mi][ni][0], acc[mi][ni][1]);
            *reinterpret_cast<float2*>(&Cb[(size_t)(r + 8) * DOUT + cc]) =
                make_float2(acc[mi][ni][2], acc[mi][ni][3]);
        }
    }
}

// ---------------------------------------------------------------------------
// Dog path: 32 (o) x 64 (t) tiles, f32x2 packed math, LDS.128 layout,
// packed fp16 EX2 (1 MUFU per 2 exponentials).
// ---------------------------------------------------------------------------
struct DogS {
    float  xn[32][72];     // [i][t_local]
    float4 pq[32][33];     // [o_local][i]
};

__device__ __forceinline__ void dog_path(int didx, char* smem,
                                         const float* __restrict__ base_w,
                                         const float* __restrict__ scale,
                                         const float* __restrict__ trans,
                                         float* __restrict__ out)
{
    DogS* S = reinterpret_cast<DogS*>(smem);   // double buffer S[0], S[1]
    int o0 = (didx & 15) * 32;
    int t0 = (didx >> 4) * 64;
    int tid = threadIdx.x;
    int tx = tid & 31, ty = tid >> 5;
    int rX = tid >> 5, cX = tid & 31;

    float2 acc[4];
    #pragma unroll
    for (int p = 0; p < 4; p++) acc[p] = make_float2(0.f, 0.f);
    const float Cc = -0.7213475204444817f;     // -0.5*log2(e)
    const float2 C2 = make_float2(Cc, Cc);

    float pxn[8], prs[4], ptr_[4], pbw[4];

    // prologue: chunk 0
    #pragma unroll
    for (int p = 0; p < 8; p++)
        pxn[p] = g_xn2[(size_t)(t0 + rX + p * 8) * DIN + cX];
    #pragma unroll
    for (int p = 0; p < 4; p++) {
        size_t oi = (size_t)(o0 + rX + p * 8) * DIN + cX;
        prs[p] = __fdividef(1.f, scale[oi]);
        ptr_[p] = trans[oi];
        pbw[p] = base_w[oi];
    }
    #pragma unroll
    for (int p = 0; p < 8; p++) S[0].xn[cX][rX + p * 8] = pxn[p];
    #pragma unroll
    for (int p = 0; p < 4; p++)
        S[0].pq[rX + p * 8][cX] = make_float4(prs[p], -ptr_[p] * prs[p], -pbw[p], 0.f);

    for (int cc = 0; cc < DIN / 32; cc++) {
        __syncthreads();
        if (cc + 1 < DIN / 32) {
            int ic = (cc + 1) * 32;
            #pragma unroll
            for (int p = 0; p < 8; p++)
                pxn[p] = g_xn2[(size_t)(t0 + rX + p * 8) * DIN + ic + cX];
            #pragma unroll
            for (int p = 0; p < 4; p++) {
                size_t oi = (size_t)(o0 + rX + p * 8) * DIN + ic + cX;
                prs[p] = __fdividef(1.f, scale[oi]);
                ptr_[p] = trans[oi];
                pbw[p] = base_w[oi];
            }
        }

        DogS& B = S[cc & 1];
        #pragma unroll 4
        for (int i = 0; i < 32; i++) {
            float4 pq = B.pq[tx][i];
            float2 rs2  = make_float2(pq.x, pq.x);
            float2 ntr2 = make_float2(pq.y, pq.y);
            float2 nbw2 = make_float2(pq.z, pq.z);
            const float4* xp = reinterpret_cast<const float4*>(&B.xn[i][ty * 8]);
            float4 xa = xp[0];
            float4 xb = xp[1];
            float2 xs[4] = { make_float2(xa.x, xa.y), make_float2(xa.z, xa.w),
                             make_float2(xb.x, xb.y), make_float2(xb.z, xb.w) };
            #pragma unroll
            for (int p = 0; p < 4; p++) {
                float2 u  = f2fma(xs[p], rs2, ntr2);
                float2 t2 = f2mul(f2mul(u, C2), u);
                float2 e  = exp2_f16x2(t2);            // 1 MUFU, 2 exps
                float2 pe = f2mul(u, e);
                acc[p] = f2fma(pe, nbw2, acc[p]);
            }
        }

        if (cc + 1 < DIN / 32) {
            DogS& Bn = S[(cc + 1) & 1];
            #pragma unroll
            for (int p = 0; p < 8; p++) Bn.xn[cX][rX + p * 8] = pxn[p];
            #pragma unroll
            for (int p = 0; p < 4; p++)
                Bn.pq[rX + p * 8][cX] = make_float4(prs[p], -ptr_[p] * prs[p], -pbw[p], 0.f);
        }
    }

    #pragma unroll
    for (int p = 0; p < 4; p++) {
        int r0 = t0 + ty * 8 + 2 * p;
        out[(size_t)(2 * T + r0) * DOUT + o0 + tx]     = acc[p].x;
        out[(size_t)(2 * T + r0 + 1) * DOUT + o0 + tx] = acc[p].y;
    }
}

__global__ void __launch_bounds__(256, 3)
fat_kernel(float* __restrict__ out,
           const float* __restrict__ base_w,
           const float* __restrict__ scale,
           const float* __restrict__ trans)
{
    extern __shared__ __align__(16) char smem[];
    int bid = blockIdx.x;
    int grp = bid / 9, rem = bid % 9;      // 576 = 9 * 64; 5 gemm + 4 dog
    if (rem < 5) gemm_path(grp * 5 + rem, smem, out);
    else         dog_path(grp * 4 + (rem - 5), smem, base_w, scale, trans, out);
}

// ---------------------------------------------------------------------------
extern "C" void kernel_launch(void* const* d_in, const int* in_sizes, int n_in,
                              void* d_out, int out_size)
{
    const float* X        = (const float*)d_in[0];
    const float* ln_w     = (const float*)d_in[1];
    const float* ln_b     = (const float*)d_in[2];
    const float* base_w   = (const float*)d_in[3];
    const float* spline_w = (const float*)d_in[4];
    const float* scale    = (const float*)d_in[5];
    const float* trans    = (const float*)d_in[6];
    const float* grid_rbf = (const float*)d_in[7];
    const float* grid_bs  = (const float*)d_in[8];
    float* out = (float*)d_out;

    cudaFuncSetAttribute(fat_kernel, cudaFuncAttributeMaxDynamicSharedMemorySize, SMEM_BYTES);

    prep_kernel<<<PREP_BLOCKS, 256>>>(X, ln_w, ln_b, spline_w, base_w,
                                      grid_rbf, grid_bs);
    fat_kernel<<<FAT_BLOCKS, 256, SMEM_BYTES>>>(out, base_w, scale, trans);
}

// round 16
// speedup vs baseline: 1.7510x; 1.0678x over previous
#include <cuda_runtime.h>
#include <cuda_fp16.h>
#include <cstdint>

// Problem constants
constexpr int Bb   = 6;
constexpr int T    = 1024;
constexpr int DIN  = 256;
constexpr int DOUT = 512;
constexpr int G    = 8;
constexpr int KSP  = DIN * G;   // 2048

// ---------------------------------------------------------------------------
// Device scratch
// ---------------------------------------------------------------------------
__device__ __align__(16) float   g_xn2[T * DIN];             // LN'd batch 2 (dog)
__device__ __align__(16) __half  g_silu[T * DIN];            // fp16 silu (batch 3)
__device__ __align__(16) __half  g_basis[4ull * T * KSP];    // fp16 basis, slots 0..3
__device__ __align__(16) __half  g_sw[DOUT * KSP];           // fp16 spline weight
__device__ __align__(16) __half  g_bw[DOUT * DIN];           // fp16 base weight

// ---------------------------------------------------------------------------
// Helpers
// ---------------------------------------------------------------------------
__device__ __forceinline__ uint32_t hpack2(__half a, __half b)
{
    __half2 p = __halves2half2(a, b);
    return *reinterpret_cast<uint32_t*>(&p);
}

__device__ __forceinline__ uint32_t smem_u32(const void* p)
{
    uint32_t a;
    asm("{ .reg .u64 t; cvta.to.shared.u64 t, %1; cvt.u32.u64 %0, t; }" : "=r"(a) : "l"(p));
    return a;
}

__device__ __forceinline__ void cpa(uint32_t d, const void* s)
{
    asm volatile("cp.async.cg.shared.global [%0], [%1], 16;" :: "r"(d), "l"(s));
}
#define CP_COMMIT() asm volatile("cp.async.commit_group;" ::: "memory")
#define CP_WAIT1()  asm volatile("cp.async.wait_group 1;"  ::: "memory")
#define CP_WAIT0()  asm volatile("cp.async.wait_group 0;"  ::: "memory")

#define LDSM_X4(R0,R1,R2,R3,ADDR) \
    asm volatile("ldmatrix.sync.aligned.m8n8.x4.shared.b16 {%0,%1,%2,%3}, [%4];" \
        : "=r"(R0), "=r"(R1), "=r"(R2), "=r"(R3) : "r"(ADDR))

__device__ __forceinline__ void mma16816(float* c, const uint32_t* a, const uint32_t* b)
{
    asm volatile(
        "mma.sync.aligned.m16n8k16.row.col.f32.f16.f16.f32 "
        "{%0,%1,%2,%3}, {%4,%5,%6,%7}, {%8,%9}, {%0,%1,%2,%3};"
        : "+f"(c[0]), "+f"(c[1]), "+f"(c[2]), "+f"(c[3])
        : "r"(a[0]), "r"(a[1]), "r"(a[2]), "r"(a[3]), "r"(b[0]), "r"(b[1]));
}

// Packed f32x2 (Blackwell)
__device__ __forceinline__ float2 f2fma(float2 a, float2 b, float2 c)
{
    float2 d;
    asm("fma.rn.f32x2 %0, %1, %2, %3;"
        : "=l"(reinterpret_cast<unsigned long long&>(d))
        : "l"(reinterpret_cast<unsigned long long&>(a)),
          "l"(reinterpret_cast<unsigned long long&>(b)),
          "l"(reinterpret_cast<unsigned long long&>(c)));
    return d;
}
__device__ __forceinline__ float2 f2mul(float2 a, float2 b)
{
    float2 d;
    asm("mul.rn.f32x2 %0, %1, %2;"
        : "=l"(reinterpret_cast<unsigned long long&>(d))
        : "l"(reinterpret_cast<unsigned long long&>(a)),
          "l"(reinterpret_cast<unsigned long long&>(b)));
    return d;
}

// Packed fp16 exp2(-n): negation folded into an ALU-pipe XOR on the half2.
__device__ __forceinline__ float2 nexp2_f16x2(float2 n)
{
    __half2 h = __float22half2_rn(n);
    uint32_t u = *reinterpret_cast<uint32_t*>(&h) ^ 0x80008000u;
    asm("ex2.approx.f16x2 %0, %0;" : "+r"(u));
    __half2 r = *reinterpret_cast<__half2*>(&u);
    return __half22float2(r);
}

// ---------------------------------------------------------------------------
// Kernel 1: fused prep (R10 structure + smem-cached ln_w/ln_b).
// ---------------------------------------------------------------------------
constexpr int LN_ROW_BLOCKS = Bb * T / 8;                 // 768
constexpr int NSP       = DOUT * KSP;                     // 1048576
constexpr int WS_ELEMS  = NSP + DOUT * DIN;               // 1179648
constexpr int WS_BLOCKS = WS_ELEMS / 1024;                // 1152
constexpr int PREP_BLOCKS = LN_ROW_BLOCKS + WS_BLOCKS;    // 1920

__global__ void prep_kernel(const float* __restrict__ X,
                            const float* __restrict__ w,
                            const float* __restrict__ bias,
                            const float* __restrict__ spline_w,
                            const float* __restrict__ base_w,
                            const float* __restrict__ grid_rbf,
                            const float* __restrict__ grid_bs)
{
    int bid = blockIdx.x;
    int tid = threadIdx.x;

    if (bid >= LN_ROW_BLOCKS) {
        int slot4 = (bid - LN_ROW_BLOCKS) * 256 + tid;
        int idx = slot4 * 4;
        const float* src = (idx < NSP) ? (spline_w + idx) : (base_w + (idx - NSP));
        float4 v = *reinterpret_cast<const float4*>(src);
        uint2 uh = make_uint2(hpack2(__float2half_rn(v.x), __float2half_rn(v.y)),
                              hpack2(__float2half_rn(v.z), __float2half_rn(v.w)));
        if (idx < NSP) {
            *reinterpret_cast<uint2*>(g_sw + idx) = uh;
        } else {
            *reinterpret_cast<uint2*>(g_bw + (idx - NSP)) = uh;
        }
        return;
    }

    __shared__ float sw_[DIN], sb_[DIN];
    sw_[tid] = w[tid];
    sb_[tid] = bias[tid];
    __syncthreads();

    int wid  = tid >> 5, lane = tid & 31;
    int row  = bid * 8 + wid;
    int bb   = row >> 10;
    int t    = row & 1023;
    const float* Xr = X + (size_t)row * DIN;

    float v[8];
    float s = 0.f, s2 = 0.f;
    #pragma unroll
    for (int j = 0; j < 8; j++) {
        v[j] = Xr[j * 32 + lane];
        s  += v[j];
        s2 += v[j] * v[j];
    }
    #pragma unroll
    for (int off = 16; off; off >>= 1) {
        s  += __shfl_xor_sync(0xffffffffu, s,  off);
        s2 += __shfl_xor_sync(0xffffffffu, s2, off);
    }
    float mu = s * (1.f / DIN);
    float rv = rsqrtf(s2 * (1.f / DIN) - mu * mu + 1e-5f);

    if (bb == 2) {
        #pragma unroll
        for (int j = 0; j < 8; j++) {
            int i = j * 32 + lane;
            float xn = (v[j] - mu) * rv * sw_[i] + sb_[i];
            g_xn2[(size_t)t * DIN + i] = xn;
        }
        return;
    }
    if (bb == 3) {
        #pragma unroll
        for (int j = 0; j < 8; j++) {
            int i = j * 32 + lane;
            float xn = (v[j] - mu) * rv * sw_[i] + sb_[i];
            float sig = 1.f / (1.f + __expf(-xn));
            g_silu[(size_t)t * DIN + i] = __float2half_rn(xn * sig);
        }
        return;
    }

    int slot = (bb == 0) ? 0 : (bb == 1) ? 1 : (bb == 4) ? 2 : 3;
    bool rbf = (bb == 0 || bb == 4);

    float gb[12], r1 = 0.f, r2 = 0.f, r3 = 0.f, gr[G];
    if (rbf) {
        #pragma unroll
        for (int g = 0; g < G; g++) gr[g] = __ldg(&grid_rbf[g]);
    } else {
        #pragma unroll
        for (int j = 0; j < 12; j++) gb[j] = __ldg(&grid_bs[j]);
        r1 = __fdividef(1.f, gb[1] - gb[0]);
        r2 = __fdividef(1.f, gb[2] - gb[0]);
        r3 = __fdividef(1.f, gb[3] - gb[0]);
    }

    #pragma unroll
    for (int j = 0; j < 8; j++) {
        int i = j * 32 + lane;
        float xn = (v[j] - mu) * rv * sw_[i] + sb_[i];
        __half h[G];
        if (rbf) {
            const float invd = 7.f / 3.f;
            const float c    = -1.4426950408889634f;
            #pragma unroll
            for (int g = 0; g < G; g++) {
                float d = (xn - gr[g]) * invd;
                h[g] = __float2half_rn(exp2f(d * d * c));
            }
        } else {
            float bsv[11];
            #pragma unroll
            for (int k = 0; k < 11; k++)
                bsv[k] = (xn >= gb[k] && xn < gb[k + 1]) ? 1.f : 0.f;
            #pragma unroll
            for (int k = 0; k <= 9; k++)
                bsv[k] = (xn - gb[k]) * r1 * bsv[k] + (gb[k + 2] - xn) * r1 * bsv[k + 1];
            #pragma unroll
            for (int k = 0; k <= 8; k++)
                bsv[k] = (xn - gb[k]) * r2 * bsv[k] + (gb[k + 3] - xn) * r2 * bsv[k + 1];
            #pragma unroll
            for (int k = 0; k <= 7; k++)
                bsv[k] = (xn - gb[k]) * r3 * bsv[k] + (gb[k + 4] - xn) * r3 * bsv[k + 1];
            #pragma unroll
            for (int k = 0; k < 8; k++) h[k] = __float2half_rn(bsv[k]);
        }
        size_t off = (size_t)slot * T * KSP + (size_t)t * KSP + i * 8;
        uint4 uh = make_uint4(hpack2(h[0],h[1]), hpack2(h[2],h[3]),
                              hpack2(h[4],h[5]), hpack2(h[6],h[7]));
        *reinterpret_cast<uint4*>(g_basis + off) = uh;
    }
}

// ---------------------------------------------------------------------------
// Fat kernel (R10 layout): 320 gemm tiles (64x128) + 256 dog tiles (32x64),
// interleaved 5 gemm : 4 dog over period 9 -> 576 CTAs.
// ---------------------------------------------------------------------------
constexpr int BM = 64, BN = 128, BK = 32;
constexpr int OFF_A = 0, OFF_W = 4096;
constexpr int STAGE  = 12288;
constexpr int NSTAGE = 3;
constexpr int SMEM_BYTES = 53248;            // max(gemm 36 KB, dog 52.2 KB)

constexpr int GEMM_TILES = 320;   // 256 spline + 64 base
constexpr int DOG_TILES  = 256;   // 16 o-tiles x 16 t-tiles (32 x 64)
constexpr int FAT_BLOCKS = GEMM_TILES + DOG_TILES;   // 576 = 9 * 64

__device__ __forceinline__ uint32_t swz(uint32_t row, uint32_t slot)
{
    return row * 64u + (((slot ^ ((row >> 1) & 3u)) & 3u) << 4);
}

__device__ __forceinline__ void gemm_path(int gidx, char* smem, float* __restrict__ out)
{
    uint32_t sbase = smem_u32(smem);
    int tid = threadIdx.x;

    int z, tt;
    if (gidx < 256) { z = gidx >> 6; tt = gidx & 63; }
    else            { z = 4;         tt = gidx - 256; }
    int mt = tt >> 2, nt = tt & 3;
    int bb = (z == 0) ? 0 : (z == 1) ? 1 : (z == 2) ? 4 : (z == 3) ? 5 : 3;

    const __half *A, *W;
    int K;
    if (z < 4) {
        A = g_basis + (size_t)z * T * KSP;
        W = g_sw; K = KSP;
    } else {
        A = g_silu;
        W = g_bw; K = DIN;
    }
    int m0 = mt * BM, n0 = nt * BN;
    int nc = K / BK;

    int lrow = tid >> 2, lslot = tid & 3;
    const __half* gA  = A + (size_t)(m0 + lrow) * K + lslot * 8;
    const __half* gW0 = W + (size_t)(n0 + lrow) * K + lslot * 8;
    const __half* gW1 = W + (size_t)(n0 + lrow + 64) * K + lslot * 8;
    uint32_t sA  = swz(lrow, lslot);
    uint32_t sW0 = swz(lrow, lslot);
    uint32_t sW1 = swz(lrow + 64, lslot);

    int lane = tid & 31, wid = tid >> 5;
    int wm = wid >> 2, wn = wid & 3;          // warp tile 32x32
    uint32_t lr  = lane & 15;
    uint32_t lks = lane >> 4;

    float acc[2][4][4];
    #pragma unroll
    for (int a = 0; a < 2; a++)
        #pragma unroll
        for (int b = 0; b < 4; b++)
            #pragma unroll
            for (int cc = 0; cc < 4; cc++) acc[a][b][cc] = 0.f;

    #pragma unroll
    for (int p = 0; p < 2; p++) {
        if (p < nc) {
            uint32_t sb = sbase + p * STAGE;
            int kc = p * BK;
            cpa(sb + OFF_A + sA,  gA + kc);
            cpa(sb + OFF_W + sW0, gW0 + kc);
            cpa(sb + OFF_W + sW1, gW1 + kc);
        }
        CP_COMMIT();
    }

    int st = 0;
    for (int c = 0; c < nc; c++) {
        CP_WAIT1();
        __syncthreads();

        if (c + 2 < nc) {
            int stn = (st + 2 >= NSTAGE) ? st + 2 - NSTAGE : st + 2;
            uint32_t sb = sbase + stn * STAGE;
            int kc = (c + 2) * BK;
            cpa(sb + OFF_A + sA,  gA + kc);
            cpa(sb + OFF_W + sW0, gW0 + kc);
            cpa(sb + OFF_W + sW1, gW1 + kc);
        }
        CP_COMMIT();

        uint32_t sb = sbase + st * STAGE;
        #pragma unroll
        for (int ks = 0; ks < 2; ks++) {
            uint32_t slot = 2 * ks + lks;
            uint32_t aF[2][4], bF[4][2];

            #pragma unroll
            for (int mi = 0; mi < 2; mi++) {
                uint32_t ad = sb + OFF_A + swz(wm * 32 + mi * 16 + lr, slot);
                LDSM_X4(aF[mi][0], aF[mi][1], aF[mi][2], aF[mi][3], ad);
            }
            #pragma unroll
            for (int p = 0; p < 2; p++) {
                uint32_t t0, t1, t2, t3;
                uint32_t ad = sb + OFF_W + swz(wn * 32 + p * 16 + lr, slot);
                LDSM_X4(t0, t1, t2, t3, ad);
                bF[2*p][0] = t0; bF[2*p][1] = t2;
                bF[2*p+1][0] = t1; bF[2*p+1][1] = t3;
            }
            #pragma unroll
            for (int mi = 0; mi < 2; mi++)
                #pragma unroll
                for (int ni = 0; ni < 4; ni++)
                    mma16816(acc[mi][ni], aF[mi], bF[ni]);
        }
        st = (st + 1 == NSTAGE) ? 0 : st + 1;
    }

    float* Cb = out + (size_t)bb * T * DOUT;
    int rbase = m0 + wm * 32 + (lane >> 2);
    int cbase = n0 + wn * 32 + (lane & 3) * 2;
    #pragma unroll
    for (int mi = 0; mi < 2; mi++) {
        #pragma unroll
        for (int ni = 0; ni < 4; ni++) {
            int r = rbase + mi * 16;
            int cc = cbase + ni * 8;
            *reinterpret_cast<float2*>(&Cb[(size_t)r * DOUT + cc]) =
                make_float2(acc[mi][ni][0], acc[mi][ni][1]);
            *reinterpret_cast<float2*>(&Cb[(size_t)(r + 8) * DOUT + cc]) =
                make_float2(acc[mi][ni][2], acc[mi][ni][3]);
        }
    }
}

// ---------------------------------------------------------------------------
// Dog path: 32 (o) x 64 (t) tiles, f32x2 packed math, LDS.128 layout,
// packed fp16 EX2; sqrt(0.5*log2e) folded into rs/tr, 1/S into -bw,
// negation via ALU XOR -> 4 fma-pipe ops per 2 elements.
// ---------------------------------------------------------------------------
struct DogS {
    float  xn[32][72];     // [i][t_local]
    float4 pq[32][33];     // [o_local][i]
};

__device__ __forceinline__ void dog_path(int didx, char* smem,
                                         const float* __restrict__ base_w,
                                         const float* __restrict__ scale,
                                         const float* __restrict__ trans,
                                         float* __restrict__ out)
{
    DogS* S = reinterpret_cast<DogS*>(smem);   // double buffer S[0], S[1]
    int o0 = (didx & 15) * 32;
    int t0 = (didx >> 4) * 64;
    int tid = threadIdx.x;
    int tx = tid & 31, ty = tid >> 5;
    int rX = tid >> 5, cX = tid & 31;

    float2 acc[4];
    #pragma unroll
    for (int p = 0; p < 4; p++) acc[p] = make_float2(0.f, 0.f);

    const float Sc  = 0.8493218803f;           // sqrt(0.5*log2(e))
    const float iSc = 1.1774100226f;           // 1/Sc

    float pxn[8], prs[4], ptr_[4], pbw[4];

    // prologue: chunk 0
    #pragma unroll
    for (int p = 0; p < 8; p++)
        pxn[p] = g_xn2[(size_t)(t0 + rX + p * 8) * DIN + cX];
    #pragma unroll
    for (int p = 0; p < 4; p++) {
        size_t oi = (size_t)(o0 + rX + p * 8) * DIN + cX;
        prs[p] = __fdividef(Sc, scale[oi]);    // rs' = Sc/scale
        ptr_[p] = trans[oi];
        pbw[p] = base_w[oi];
    }
    #pragma unroll
    for (int p = 0; p < 8; p++) S[0].xn[cX][rX + p * 8] = pxn[p];
    #pragma unroll
    for (int p = 0; p < 4; p++)
        S[0].pq[rX + p * 8][cX] =
            make_float4(prs[p], -ptr_[p] * prs[p], -pbw[p] * iSc, 0.f);

    for (int cc = 0; cc < DIN / 32; cc++) {
        __syncthreads();
        if (cc + 1 < DIN / 32) {
            int ic = (cc + 1) * 32;
            #pragma unroll
            for (int p = 0; p < 8; p++)
                pxn[p] = g_xn2[(size_t)(t0 + rX + p * 8) * DIN + ic + cX];
            #pragma unroll
            for (int p = 0; p < 4; p++) {
                size_t oi = (size_t)(o0 + rX + p * 8) * DIN + ic + cX;
                prs[p] = __fdividef(Sc, scale[oi]);
                ptr_[p] = trans[oi];
                pbw[p] = base_w[oi];
            }
        }

        DogS& B = S[cc & 1];
        #pragma unroll 4
        for (int i = 0; i < 32; i++) {
            float4 pq = B.pq[tx][i];
            float2 rs2  = make_float2(pq.x, pq.x);
            float2 ntr2 = make_float2(pq.y, pq.y);
            float2 nbw2 = make_float2(pq.z, pq.z);
            const float4* xp = reinterpret_cast<const float4*>(&B.xn[i][ty * 8]);
            float4 xa = xp[0];
            float4 xb = xp[1];
            float2 xs[4] = { make_float2(xa.x, xa.y), make_float2(xa.z, xa.w),
                             make_float2(xb.x, xb.y), make_float2(xb.z, xb.w) };
            #pragma unroll
            for (int p = 0; p < 4; p++) {
                float2 u = f2fma(xs[p], rs2, ntr2);    // u' = Sc*u
                float2 n = f2mul(u, u);                // n = u'^2 >= 0
                float2 e = nexp2_f16x2(n);             // exp2(-n), 1 MUFU / 2 exps
                float2 pe = f2mul(u, e);
                acc[p] = f2fma(pe, nbw2, acc[p]);
            }
        }

        if (cc + 1 < DIN / 32) {
            DogS& Bn = S[(cc + 1) & 1];
            #pragma unroll
            for (int p = 0; p < 8; p++) Bn.xn[cX][rX + p * 8] = pxn[p];
            #pragma unroll
            for (int p = 0; p < 4; p++)
                Bn.pq[rX + p * 8][cX] =
                    make_float4(prs[p], -ptr_[p] * prs[p], -pbw[p] * iSc, 0.f);
        }
    }

    #pragma unroll
    for (int p = 0; p < 4; p++) {
        int r0 = t0 + ty * 8 + 2 * p;
        out[(size_t)(2 * T + r0) * DOUT + o0 + tx]     = acc[p].x;
        out[(size_t)(2 * T + r0 + 1) * DOUT + o0 + tx] = acc[p].y;
    }
}

__global__ void __launch_bounds__(256, 3)
fat_kernel(float* __restrict__ out,
           const float* __restrict__ base_w,
           const float* __restrict__ scale,
           const float* __restrict__ trans)
{
    extern __shared__ __align__(16) char smem[];
    int bid = blockIdx.x;
    int grp = bid / 9, rem = bid % 9;      // 576 = 9 * 64; 5 gemm + 4 dog
    if (rem < 5) gemm_path(grp * 5 + rem, smem, out);
    else         dog_path(grp * 4 + (rem - 5), smem, base_w, scale, trans, out);
}

// ---------------------------------------------------------------------------
extern "C" void kernel_launch(void* const* d_in, const int* in_sizes, int n_in,
                              void* d_out, int out_size)
{
    const float* X        = (const float*)d_in[0];
    const float* ln_w     = (const float*)d_in[1];
    const float* ln_b     = (const float*)d_in[2];
    const float* base_w   = (const float*)d_in[3];
    const float* spline_w = (const float*)d_in[4];
    const float* scale    = (const float*)d_in[5];
    const float* trans    = (const float*)d_in[6];
    const float* grid_rbf = (const float*)d_in[7];
    const float* grid_bs  = (const float*)d_in[8];
    float* out = (float*)d_out;

    cudaFuncSetAttribute(fat_kernel, cudaFuncAttributeMaxDynamicSharedMemorySize, SMEM_BYTES);

    prep_kernel<<<PREP_BLOCKS, 256>>>(X, ln_w, ln_b, spline_w, base_w,
                                      grid_rbf, grid_bs);
    fat_kernel<<<FAT_BLOCKS, 256, SMEM_BYTES>>>(out, base_w, scale, trans);
}

// round 17
// speedup vs baseline: 1.7529x; 1.0011x over previous
#include <cuda_runtime.h>
#include <cuda_fp16.h>
#include <cstdint>

// Problem constants
constexpr int Bb   = 6;
constexpr int T    = 1024;
constexpr int DIN  = 256;
constexpr int DOUT = 512;
constexpr int G    = 8;
constexpr int KSP  = DIN * G;   // 2048

// ---------------------------------------------------------------------------
// Device scratch
// ---------------------------------------------------------------------------
__device__ __align__(16) float   g_xn2[T * DIN];             // LN'd batch 2 (dog)
__device__ __align__(16) __half  g_silu[T * DIN];            // fp16 silu (batch 3)
__device__ __align__(16) __half  g_basis[4ull * T * KSP];    // fp16 basis, slots 0..3
__device__ __align__(16) __half  g_sw[DOUT * KSP];           // fp16 spline weight
__device__ __align__(16) __half  g_bw[DOUT * DIN];           // fp16 base weight

// ---------------------------------------------------------------------------
// Helpers
// ---------------------------------------------------------------------------
__device__ __forceinline__ uint32_t hpack2(__half a, __half b)
{
    __half2 p = __halves2half2(a, b);
    return *reinterpret_cast<uint32_t*>(&p);
}

__device__ __forceinline__ uint32_t smem_u32(const void* p)
{
    uint32_t a;
    asm("{ .reg .u64 t; cvta.to.shared.u64 t, %1; cvt.u32.u64 %0, t; }" : "=r"(a) : "l"(p));
    return a;
}

__device__ __forceinline__ void cpa(uint32_t d, const void* s)
{
    asm volatile("cp.async.cg.shared.global [%0], [%1], 16;" :: "r"(d), "l"(s));
}
#define CP_COMMIT() asm volatile("cp.async.commit_group;" ::: "memory")
#define CP_WAIT1()  asm volatile("cp.async.wait_group 1;"  ::: "memory")
#define CP_WAIT0()  asm volatile("cp.async.wait_group 0;"  ::: "memory")

#define LDSM_X4(R0,R1,R2,R3,ADDR) \
    asm volatile("ldmatrix.sync.aligned.m8n8.x4.shared.b16 {%0,%1,%2,%3}, [%4];" \
        : "=r"(R0), "=r"(R1), "=r"(R2), "=r"(R3) : "r"(ADDR))

__device__ __forceinline__ void mma16816(float* c, const uint32_t* a, const uint32_t* b)
{
    asm volatile(
        "mma.sync.aligned.m16n8k16.row.col.f32.f16.f16.f32 "
        "{%0,%1,%2,%3}, {%4,%5,%6,%7}, {%8,%9}, {%0,%1,%2,%3};"
        : "+f"(c[0]), "+f"(c[1]), "+f"(c[2]), "+f"(c[3])
        : "r"(a[0]), "r"(a[1]), "r"(a[2]), "r"(a[3]), "r"(b[0]), "r"(b[1]));
}

// Packed f32x2 (Blackwell)
__device__ __forceinline__ float2 f2fma(float2 a, float2 b, float2 c)
{
    float2 d;
    asm("fma.rn.f32x2 %0, %1, %2, %3;"
        : "=l"(reinterpret_cast<unsigned long long&>(d))
        : "l"(reinterpret_cast<unsigned long long&>(a)),
          "l"(reinterpret_cast<unsigned long long&>(b)),
          "l"(reinterpret_cast<unsigned long long&>(c)));
    return d;
}
__device__ __forceinline__ float2 f2mul(float2 a, float2 b)
{
    float2 d;
    asm("mul.rn.f32x2 %0, %1, %2;"
        : "=l"(reinterpret_cast<unsigned long long&>(d))
        : "l"(reinterpret_cast<unsigned long long&>(a)),
          "l"(reinterpret_cast<unsigned long long&>(b)));
    return d;
}

// Packed fp16 exp2(-n): negation folded into an ALU-pipe XOR on the half2.
__device__ __forceinline__ float2 nexp2_f16x2(float2 n)
{
    __half2 h = __float22half2_rn(n);
    uint32_t u = *reinterpret_cast<uint32_t*>(&h) ^ 0x80008000u;
    asm("ex2.approx.f16x2 %0, %0;" : "+r"(u));
    __half2 r = *reinterpret_cast<__half2*>(&u);
    return __half22float2(r);
}

// ---------------------------------------------------------------------------
// Kernel 1: fused prep (R16).
// ---------------------------------------------------------------------------
constexpr int LN_ROW_BLOCKS = Bb * T / 8;                 // 768
constexpr int NSP       = DOUT * KSP;                     // 1048576
constexpr int WS_ELEMS  = NSP + DOUT * DIN;               // 1179648
constexpr int WS_BLOCKS = WS_ELEMS / 1024;                // 1152
constexpr int PREP_BLOCKS = LN_ROW_BLOCKS + WS_BLOCKS;    // 1920

__global__ void prep_kernel(const float* __restrict__ X,
                            const float* __restrict__ w,
                            const float* __restrict__ bias,
                            const float* __restrict__ spline_w,
                            const float* __restrict__ base_w,
                            const float* __restrict__ grid_rbf,
                            const float* __restrict__ grid_bs)
{
    int bid = blockIdx.x;
    int tid = threadIdx.x;

    if (bid >= LN_ROW_BLOCKS) {
        int slot4 = (bid - LN_ROW_BLOCKS) * 256 + tid;
        int idx = slot4 * 4;
        const float* src = (idx < NSP) ? (spline_w + idx) : (base_w + (idx - NSP));
        float4 v = *reinterpret_cast<const float4*>(src);
        uint2 uh = make_uint2(hpack2(__float2half_rn(v.x), __float2half_rn(v.y)),
                              hpack2(__float2half_rn(v.z), __float2half_rn(v.w)));
        if (idx < NSP) {
            *reinterpret_cast<uint2*>(g_sw + idx) = uh;
        } else {
            *reinterpret_cast<uint2*>(g_bw + (idx - NSP)) = uh;
        }
        return;
    }

    __shared__ float sw_[DIN], sb_[DIN];
    sw_[tid] = w[tid];
    sb_[tid] = bias[tid];
    __syncthreads();

    int wid  = tid >> 5, lane = tid & 31;
    int row  = bid * 8 + wid;
    int bb   = row >> 10;
    int t    = row & 1023;
    const float* Xr = X + (size_t)row * DIN;

    float v[8];
    float s = 0.f, s2 = 0.f;
    #pragma unroll
    for (int j = 0; j < 8; j++) {
        v[j] = Xr[j * 32 + lane];
        s  += v[j];
        s2 += v[j] * v[j];
    }
    #pragma unroll
    for (int off = 16; off; off >>= 1) {
        s  += __shfl_xor_sync(0xffffffffu, s,  off);
        s2 += __shfl_xor_sync(0xffffffffu, s2, off);
    }
    float mu = s * (1.f / DIN);
    float rv = rsqrtf(s2 * (1.f / DIN) - mu * mu + 1e-5f);

    if (bb == 2) {
        #pragma unroll
        for (int j = 0; j < 8; j++) {
            int i = j * 32 + lane;
            float xn = (v[j] - mu) * rv * sw_[i] + sb_[i];
            g_xn2[(size_t)t * DIN + i] = xn;
        }
        return;
    }
    if (bb == 3) {
        #pragma unroll
        for (int j = 0; j < 8; j++) {
            int i = j * 32 + lane;
            float xn = (v[j] - mu) * rv * sw_[i] + sb_[i];
            float sig = 1.f / (1.f + __expf(-xn));
            g_silu[(size_t)t * DIN + i] = __float2half_rn(xn * sig);
        }
        return;
    }

    int slot = (bb == 0) ? 0 : (bb == 1) ? 1 : (bb == 4) ? 2 : 3;
    bool rbf = (bb == 0 || bb == 4);

    float gb[12], r1 = 0.f, r2 = 0.f, r3 = 0.f, gr[G];
    if (rbf) {
        #pragma unroll
        for (int g = 0; g < G; g++) gr[g] = __ldg(&grid_rbf[g]);
    } else {
        #pragma unroll
        for (int j = 0; j < 12; j++) gb[j] = __ldg(&grid_bs[j]);
        r1 = __fdividef(1.f, gb[1] - gb[0]);
        r2 = __fdividef(1.f, gb[2] - gb[0]);
        r3 = __fdividef(1.f, gb[3] - gb[0]);
    }

    #pragma unroll
    for (int j = 0; j < 8; j++) {
        int i = j * 32 + lane;
        float xn = (v[j] - mu) * rv * sw_[i] + sb_[i];
        __half h[G];
        if (rbf) {
            const float invd = 7.f / 3.f;
            const float c    = -1.4426950408889634f;
            #pragma unroll
            for (int g = 0; g < G; g++) {
                float d = (xn - gr[g]) * invd;
                h[g] = __float2half_rn(exp2f(d * d * c));
            }
        } else {
            float bsv[11];
            #pragma unroll
            for (int k = 0; k < 11; k++)
                bsv[k] = (xn >= gb[k] && xn < gb[k + 1]) ? 1.f : 0.f;
            #pragma unroll
            for (int k = 0; k <= 9; k++)
                bsv[k] = (xn - gb[k]) * r1 * bsv[k] + (gb[k + 2] - xn) * r1 * bsv[k + 1];
            #pragma unroll
            for (int k = 0; k <= 8; k++)
                bsv[k] = (xn - gb[k]) * r2 * bsv[k] + (gb[k + 3] - xn) * r2 * bsv[k + 1];
            #pragma unroll
            for (int k = 0; k <= 7; k++)
                bsv[k] = (xn - gb[k]) * r3 * bsv[k] + (gb[k + 4] - xn) * r3 * bsv[k + 1];
            #pragma unroll
            for (int k = 0; k < 8; k++) h[k] = __float2half_rn(bsv[k]);
        }
        size_t off = (size_t)slot * T * KSP + (size_t)t * KSP + i * 8;
        uint4 uh = make_uint4(hpack2(h[0],h[1]), hpack2(h[2],h[3]),
                              hpack2(h[4],h[5]), hpack2(h[6],h[7]));
        *reinterpret_cast<uint4*>(g_basis + off) = uh;
    }
}

// ---------------------------------------------------------------------------
// Fat kernel (R10 layout): 320 gemm tiles (64x128) + 256 dog tiles (32x64),
// interleaved 5 gemm : 4 dog over period 9 -> 576 CTAs. 4 CTA/SM target.
// ---------------------------------------------------------------------------
constexpr int BM = 64, BN = 128, BK = 32;
constexpr int OFF_A = 0, OFF_W = 4096;
constexpr int STAGE  = 12288;
constexpr int NSTAGE = 3;
constexpr int SMEM_BYTES = 53248;            // max(gemm 36 KB, dog 52.2 KB)

constexpr int GEMM_TILES = 320;   // 256 spline + 64 base
constexpr int DOG_TILES  = 256;   // 16 o-tiles x 16 t-tiles (32 x 64)
constexpr int FAT_BLOCKS = GEMM_TILES + DOG_TILES;   // 576 = 9 * 64

__device__ __forceinline__ uint32_t swz(uint32_t row, uint32_t slot)
{
    return row * 64u + (((slot ^ ((row >> 1) & 3u)) & 3u) << 4);
}

__device__ __forceinline__ void gemm_path(int gidx, char* smem, float* __restrict__ out)
{
    uint32_t sbase = smem_u32(smem);
    int tid = threadIdx.x;

    int z, tt;
    if (gidx < 256) { z = gidx >> 6; tt = gidx & 63; }
    else            { z = 4;         tt = gidx - 256; }
    int mt = tt >> 2, nt = tt & 3;
    int bb = (z == 0) ? 0 : (z == 1) ? 1 : (z == 2) ? 4 : (z == 3) ? 5 : 3;

    const __half *A, *W;
    int K;
    if (z < 4) {
        A = g_basis + (size_t)z * T * KSP;
        W = g_sw; K = KSP;
    } else {
        A = g_silu;
        W = g_bw; K = DIN;
    }
    int m0 = mt * BM, n0 = nt * BN;
    int nc = K / BK;

    int lrow = tid >> 2, lslot = tid & 3;
    const __half* gA  = A + (size_t)(m0 + lrow) * K + lslot * 8;
    const __half* gW0 = W + (size_t)(n0 + lrow) * K + lslot * 8;
    const __half* gW1 = W + (size_t)(n0 + lrow + 64) * K + lslot * 8;
    uint32_t sA  = swz(lrow, lslot);
    uint32_t sW0 = swz(lrow, lslot);
    uint32_t sW1 = swz(lrow + 64, lslot);

    int lane = tid & 31, wid = tid >> 5;
    int wm = wid >> 2, wn = wid & 3;          // warp tile 32x32
    uint32_t lr  = lane & 15;
    uint32_t lks = lane >> 4;

    float acc[2][4][4];
    #pragma unroll
    for (int a = 0; a < 2; a++)
        #pragma unroll
        for (int b = 0; b < 4; b++)
            #pragma unroll
            for (int cc = 0; cc < 4; cc++) acc[a][b][cc] = 0.f;

    #pragma unroll
    for (int p = 0; p < 2; p++) {
        if (p < nc) {
            uint32_t sb = sbase + p * STAGE;
            int kc = p * BK;
            cpa(sb + OFF_A + sA,  gA + kc);
            cpa(sb + OFF_W + sW0, gW0 + kc);
            cpa(sb + OFF_W + sW1, gW1 + kc);
        }
        CP_COMMIT();
    }

    int st = 0;
    for (int c = 0; c < nc; c++) {
        CP_WAIT1();
        __syncthreads();

        if (c + 2 < nc) {
            int stn = (st + 2 >= NSTAGE) ? st + 2 - NSTAGE : st + 2;
            uint32_t sb = sbase + stn * STAGE;
            int kc = (c + 2) * BK;
            cpa(sb + OFF_A + sA,  gA + kc);
            cpa(sb + OFF_W + sW0, gW0 + kc);
            cpa(sb + OFF_W + sW1, gW1 + kc);
        }
        CP_COMMIT();

        uint32_t sb = sbase + st * STAGE;
        #pragma unroll
        for (int ks = 0; ks < 2; ks++) {
            uint32_t slot = 2 * ks + lks;
            uint32_t aF[2][4], bF[4][2];

            #pragma unroll
            for (int mi = 0; mi < 2; mi++) {
                uint32_t ad = sb + OFF_A + swz(wm * 32 + mi * 16 + lr, slot);
                LDSM_X4(aF[mi][0], aF[mi][1], aF[mi][2], aF[mi][3], ad);
            }
            #pragma unroll
            for (int p = 0; p < 2; p++) {
                uint32_t t0, t1, t2, t3;
                uint32_t ad = sb + OFF_W + swz(wn * 32 + p * 16 + lr, slot);
                LDSM_X4(t0, t1, t2, t3, ad);
                bF[2*p][0] = t0; bF[2*p][1] = t2;
                bF[2*p+1][0] = t1; bF[2*p+1][1] = t3;
            }
            #pragma unroll
            for (int mi = 0; mi < 2; mi++)
                #pragma unroll
                for (int ni = 0; ni < 4; ni++)
                    mma16816(acc[mi][ni], aF[mi], bF[ni]);
        }
        st = (st + 1 == NSTAGE) ? 0 : st + 1;
    }

    float* Cb = out + (size_t)bb * T * DOUT;
    int rbase = m0 + wm * 32 + (lane >> 2);
    int cbase = n0 + wn * 32 + (lane & 3) * 2;
    #pragma unroll
    for (int mi = 0; mi < 2; mi++) {
        #pragma unroll
        for (int ni = 0; ni < 4; ni++) {
            int r = rbase + mi * 16;
            int cc = cbase + ni * 8;
            *reinterpret_cast<float2*>(&Cb[(size_t)r * DOUT + cc]) =
                make_float2(acc[mi][ni][0], acc[mi][ni][1]);
            *reinterpret_cast<float2*>(&Cb[(size_t)(r + 8) * DOUT + cc]) =
                make_float2(acc[mi][ni][2], acc[mi][ni][3]);
        }
    }
}

// ---------------------------------------------------------------------------
// Dog path: 32 (o) x 64 (t) tiles, f32x2 packed math, LDS.128 layout,
// packed fp16 EX2; scale folded (R16).
// ---------------------------------------------------------------------------
struct DogS {
    float  xn[32][72];     // [i][t_local]
    float4 pq[32][33];     // [o_local][i]
};

__device__ __forceinline__ void dog_path(int didx, char* smem,
                                         const float* __restrict__ base_w,
                                         const float* __restrict__ scale,
                                         const float* __restrict__ trans,
                                         float* __restrict__ out)
{
    DogS* S = reinterpret_cast<DogS*>(smem);   // double buffer S[0], S[1]
    int o0 = (didx & 15) * 32;
    int t0 = (didx >> 4) * 64;
    int tid = threadIdx.x;
    int tx = tid & 31, ty = tid >> 5;
    int rX = tid >> 5, cX = tid & 31;

    float2 acc[4];
    #pragma unroll
    for (int p = 0; p < 4; p++) acc[p] = make_float2(0.f, 0.f);

    const float Sc  = 0.8493218803f;           // sqrt(0.5*log2(e))
    const float iSc = 1.1774100226f;           // 1/Sc

    float pxn[8], prs[4], ptr_[4], pbw[4];

    // prologue: chunk 0
    #pragma unroll
    for (int p = 0; p < 8; p++)
        pxn[p] = g_xn2[(size_t)(t0 + rX + p * 8) * DIN + cX];
    #pragma unroll
    for (int p = 0; p < 4; p++) {
        size_t oi = (size_t)(o0 + rX + p * 8) * DIN + cX;
        prs[p] = __fdividef(Sc, scale[oi]);    // rs' = Sc/scale
        ptr_[p] = trans[oi];
        pbw[p] = base_w[oi];
    }
    #pragma unroll
    for (int p = 0; p < 8; p++) S[0].xn[cX][rX + p * 8] = pxn[p];
    #pragma unroll
    for (int p = 0; p < 4; p++)
        S[0].pq[rX + p * 8][cX] =
            make_float4(prs[p], -ptr_[p] * prs[p], -pbw[p] * iSc, 0.f);

    for (int cc = 0; cc < DIN / 32; cc++) {
        __syncthreads();
        if (cc + 1 < DIN / 32) {
            int ic = (cc + 1) * 32;
            #pragma unroll
            for (int p = 0; p < 8; p++)
                pxn[p] = g_xn2[(size_t)(t0 + rX + p * 8) * DIN + ic + cX];
            #pragma unroll
            for (int p = 0; p < 4; p++) {
                size_t oi = (size_t)(o0 + rX + p * 8) * DIN + ic + cX;
                prs[p] = __fdividef(Sc, scale[oi]);
                ptr_[p] = trans[oi];
                pbw[p] = base_w[oi];
            }
        }

        DogS& B = S[cc & 1];
        #pragma unroll 4
        for (int i = 0; i < 32; i++) {
            float4 pq = B.pq[tx][i];
            float2 rs2  = make_float2(pq.x, pq.x);
            float2 ntr2 = make_float2(pq.y, pq.y);
            float2 nbw2 = make_float2(pq.z, pq.z);
            const float4* xp = reinterpret_cast<const float4*>(&B.xn[i][ty * 8]);
            float4 xa = xp[0];
            float4 xb = xp[1];
            float2 xs[4] = { make_float2(xa.x, xa.y), make_float2(xa.z, xa.w),
                             make_float2(xb.x, xb.y), make_float2(xb.z, xb.w) };
            #pragma unroll
            for (int p = 0; p < 4; p++) {
                float2 u = f2fma(xs[p], rs2, ntr2);    // u' = Sc*u
                float2 n = f2mul(u, u);                // n = u'^2 >= 0
                float2 e = nexp2_f16x2(n);             // exp2(-n), 1 MUFU / 2 exps
                float2 pe = f2mul(u, e);
                acc[p] = f2fma(pe, nbw2, acc[p]);
            }
        }

        if (cc + 1 < DIN / 32) {
            DogS& Bn = S[(cc + 1) & 1];
            #pragma unroll
            for (int p = 0; p < 8; p++) Bn.xn[cX][rX + p * 8] = pxn[p];
            #pragma unroll
            for (int p = 0; p < 4; p++)
                Bn.pq[rX + p * 8][cX] =
                    make_float4(prs[p], -ptr_[p] * prs[p], -pbw[p] * iSc, 0.f);
        }
    }

    #pragma unroll
    for (int p = 0; p < 4; p++) {
        int r0 = t0 + ty * 8 + 2 * p;
        out[(size_t)(2 * T + r0) * DOUT + o0 + tx]     = acc[p].x;
        out[(size_t)(2 * T + r0 + 1) * DOUT + o0 + tx] = acc[p].y;
    }
}

__global__ void __launch_bounds__(256, 4)
fat_kernel(float* __restrict__ out,
           const float* __restrict__ base_w,
           const float* __restrict__ scale,
           const float* __restrict__ trans)
{
    extern __shared__ __align__(16) char smem[];
    int bid = blockIdx.x;
    int grp = bid / 9, rem = bid % 9;      // 576 = 9 * 64; 5 gemm + 4 dog
    if (rem < 5) gemm_path(grp * 5 + rem, smem, out);
    else         dog_path(grp * 4 + (rem - 5), smem, base_w, scale, trans, out);
}

// ---------------------------------------------------------------------------
extern "C" void kernel_launch(void* const* d_in, const int* in_sizes, int n_in,
                              void* d_out, int out_size)
{
    const float* X        = (const float*)d_in[0];
    const float* ln_w     = (const float*)d_in[1];
    const float* ln_b     = (const float*)d_in[2];
    const float* base_w   = (const float*)d_in[3];
    const float* spline_w = (const float*)d_in[4];
    const float* scale    = (const float*)d_in[5];
    const float* trans    = (const float*)d_in[6];
    const float* grid_rbf = (const float*)d_in[7];
    const float* grid_bs  = (const float*)d_in[8];
    float* out = (float*)d_out;

    cudaFuncSetAttribute(fat_kernel, cudaFuncAttributeMaxDynamicSharedMemorySize, SMEM_BYTES);

    prep_kernel<<<PREP_BLOCKS, 256>>>(X, ln_w, ln_b, spline_w, base_w,
                                      grid_rbf, grid_bs);
    fat_kernel<<<FAT_BLOCKS, 256, SMEM_BYTES>>>(out, base_w, scale, trans);
}